// round 1
// baseline (speedup 1.0000x reference)
#include <cuda_runtime.h>
#include <cstdint>

#define ROWS_TOTAL 16384
#define BATCH 4
#define SEQ 4096
#define DIM 2048
#define DSMALL 64
#define NTOT 4096
#define NC 2048

// ---------------- device scratch (static, no runtime alloc) ----------------
__device__ float g_embn_t[DSMALL * NTOT];                 // [k][n]  1 MB, normalized emb, transposed
__device__ float g_Ht[DSMALL * ROWS_TOTAL];               // [k][row] 4 MB, h transposed
__device__ float g_logits[(size_t)ROWS_TOTAL * NTOT];     // 268 MB logits scratch
__device__ float g_part[512 * NTOT];                      // 8 MB per-CTA partial d
__device__ float g_d[BATCH * NTOT];                       // final d

// ---------------- fast exp (FFMA-only, avoids MUFU bottleneck) -------------
__device__ __forceinline__ float fexp(float x) {
    x = fmaxf(x, -87.0f);
    float y = x * 1.4426950408889634f;      // x * log2(e)
    float n = rintf(y);
    float t = (y - n) * 0.6931471805599453f; // |t| <= 0.3466
    float p = fmaf(t, 8.3333333e-3f, 4.1666667e-2f); // 1/120, 1/24
    p = fmaf(p, t, 0.16666667f);
    p = fmaf(p, t, 0.5f);
    p = fmaf(p, t, 1.0f);
    p = fmaf(p, t, 1.0f);
    int e = (int)n;
    float s = __int_as_float((e + 127) << 23);
    return p * s;
}

// ---------------- K1: normalize neuron_emb, store transposed ---------------
__global__ void k_norm_emb(const float* __restrict__ emb) {
    int n = blockIdx.x * 8 + (threadIdx.x >> 5);
    int lane = threadIdx.x & 31;
    float v0 = emb[n * 64 + lane];
    float v1 = emb[n * 64 + lane + 32];
    float ss = v0 * v0 + v1 * v1;
    #pragma unroll
    for (int o = 16; o; o >>= 1) ss += __shfl_xor_sync(0xffffffffu, ss, o);
    float inv = rsqrtf(ss);
    g_embn_t[lane * NTOT + n] = v0 * inv;
    g_embn_t[(lane + 32) * NTOT + n] = v1 * inv;
}

// ---------------- K2: H = X @ W + b  (writes Ht[k][row]) -------------------
// CTA: 64 rows x 64 cols, 256 threads, thread tile 4x4, K chunks of 32.
__global__ void k_gemm1(const float* __restrict__ X, const float* __restrict__ W,
                        const float* __restrict__ bias) {
    __shared__ float xt[32][68];   // [k][row], padded (68*4=272=17*16 keeps 16B align)
    __shared__ float ws[32][64];   // [k][col]
    int tid = threadIdx.x;
    int tc = tid & 15, tr = tid >> 4;
    int rowbase = blockIdx.x * 64;
    float acc[4][4] = {};

    for (int kb = 0; kb < DIM; kb += 32) {
        #pragma unroll
        for (int u = 0; u < 2; u++) {
            int fidx = tid + u * 256;          // 0..511
            int row = fidx >> 3;               // 0..63
            int k4 = (fidx & 7) * 4;           // 0..28
            float4 v = *(const float4*)&X[(size_t)(rowbase + row) * DIM + kb + k4];
            xt[k4][row] = v.x; xt[k4 + 1][row] = v.y;
            xt[k4 + 2][row] = v.z; xt[k4 + 3][row] = v.w;
        }
        #pragma unroll
        for (int u = 0; u < 2; u++) {
            int fidx = tid + u * 256;
            int k = fidx >> 4;
            int c4 = (fidx & 15) * 4;
            *(float4*)&ws[k][c4] = *(const float4*)&W[(size_t)(kb + k) * 64 + c4];
        }
        __syncthreads();
        #pragma unroll 8
        for (int k = 0; k < 32; k++) {
            float4 xv = *(float4*)&xt[k][tr * 4];
            float4 wv = *(float4*)&ws[k][tc * 4];
            float xs[4] = {xv.x, xv.y, xv.z, xv.w};
            float wsv[4] = {wv.x, wv.y, wv.z, wv.w};
            #pragma unroll
            for (int i = 0; i < 4; i++)
                #pragma unroll
                for (int j = 0; j < 4; j++)
                    acc[i][j] = fmaf(xs[i], wsv[j], acc[i][j]);
        }
        __syncthreads();
    }
    #pragma unroll
    for (int j = 0; j < 4; j++) {
        int c = tc * 4 + j;
        float bb = bias[c];
        float4 v = make_float4(acc[0][j] + bb, acc[1][j] + bb,
                               acc[2][j] + bb, acc[3][j] + bb);
        *(float4*)&g_Ht[(size_t)c * ROWS_TOTAL + rowbase + tr * 4] = v;
    }
}

// ---------------- K3: logits = H @ embn^T (K=64, single chunk) -------------
// CTA: 64 rows x 128 neurons, 256 threads, thread tile 4x8.
__global__ void k_gemm2() {
    __shared__ float ht[64][64];    // [k][row]
    __shared__ float et[64][128];   // [k][n]
    int tid = threadIdx.x;
    int tn = tid & 15, tr = tid >> 4;
    int nbase = blockIdx.x * 128;
    int rowbase = blockIdx.y * 64;

    #pragma unroll
    for (int u = 0; u < 4; u++) {
        int fidx = tid + u * 256;           // 0..1023
        int k = fidx >> 4; int r4 = (fidx & 15) * 4;
        *(float4*)&ht[k][r4] = *(const float4*)&g_Ht[(size_t)k * ROWS_TOTAL + rowbase + r4];
    }
    #pragma unroll
    for (int u = 0; u < 8; u++) {
        int fidx = tid + u * 256;           // 0..2047
        int k = fidx >> 5; int n4 = (fidx & 31) * 4;
        *(float4*)&et[k][n4] = *(const float4*)&g_embn_t[(size_t)k * NTOT + nbase + n4];
    }
    __syncthreads();

    float acc[4][8] = {};
    #pragma unroll 16
    for (int k = 0; k < 64; k++) {
        float4 hv = *(float4*)&ht[k][tr * 4];
        float4 e0 = *(float4*)&et[k][tn * 4];
        float4 e1 = *(float4*)&et[k][64 + tn * 4];
        float hs[4] = {hv.x, hv.y, hv.z, hv.w};
        float es[8] = {e0.x, e0.y, e0.z, e0.w, e1.x, e1.y, e1.z, e1.w};
        #pragma unroll
        for (int i = 0; i < 4; i++)
            #pragma unroll
            for (int j = 0; j < 8; j++)
                acc[i][j] = fmaf(hs[i], es[j], acc[i][j]);
    }
    #pragma unroll
    for (int i = 0; i < 4; i++) {
        size_t ro = (size_t)(rowbase + tr * 4 + i) * NTOT + nbase;
        *(float4*)&g_logits[ro + tn * 4] =
            make_float4(acc[i][0], acc[i][1], acc[i][2], acc[i][3]);
        *(float4*)&g_logits[ro + 64 + tn * 4] =
            make_float4(acc[i][4], acc[i][5], acc[i][6], acc[i][7]);
    }
}

// ------- K4: per-row 3-group softmax, importance-weighted accumulate -------
// CTA handles 32 consecutive rows (same b). Thread owns n = tid*16 .. tid*16+15,
// so each thread belongs to exactly one softmax group:
//   tid <128 -> group C (n<2048), tid 128..191 -> QK, tid 192..255 -> V.
__global__ void k_softmax(const float* __restrict__ imp) {
    int tid = threadIdx.x;
    int lane = tid & 31, wid = tid >> 5;
    int rb = blockIdx.x * 32;
    __shared__ float wred[8];
    float acc[16] = {};
    int grp = (tid < 128) ? 0 : (tid < 192 ? 1 : 2);

    for (int ri = 0; ri < 32; ri++) {
        int r = rb + ri;
        const float4* lp = (const float4*)(g_logits + (size_t)r * NTOT);
        float lg[16];
        #pragma unroll
        for (int q = 0; q < 4; q++) {
            float4 v = lp[tid * 4 + q];
            lg[q * 4] = v.x; lg[q * 4 + 1] = v.y; lg[q * 4 + 2] = v.z; lg[q * 4 + 3] = v.w;
        }
        // group max
        float m = -1e30f;
        #pragma unroll
        for (int j = 0; j < 16; j++) m = fmaxf(m, lg[j]);
        #pragma unroll
        for (int o = 16; o; o >>= 1) m = fmaxf(m, __shfl_xor_sync(0xffffffffu, m, o));
        if (lane == 0) wred[wid] = m;
        __syncthreads();
        float gm;
        if (grp == 0) gm = fmaxf(fmaxf(wred[0], wred[1]), fmaxf(wred[2], wred[3]));
        else if (grp == 1) gm = fmaxf(wred[4], wred[5]);
        else gm = fmaxf(wred[6], wred[7]);
        __syncthreads();
        // exp + group sum
        float e[16]; float se = 0.0f;
        #pragma unroll
        for (int j = 0; j < 16; j++) { e[j] = fexp(lg[j] - gm); se += e[j]; }
        #pragma unroll
        for (int o = 16; o; o >>= 1) se += __shfl_xor_sync(0xffffffffu, se, o);
        if (lane == 0) wred[wid] = se;
        __syncthreads();
        float gs;
        if (grp == 0) gs = (wred[0] + wred[1]) + (wred[2] + wred[3]);
        else if (grp == 1) gs = wred[4] + wred[5];
        else gs = wred[6] + wred[7];
        __syncthreads();
        float sc = imp[r] / gs;
        #pragma unroll
        for (int j = 0; j < 16; j++) acc[j] = fmaf(e[j], sc, acc[j]);
    }
    float* pp = g_part + (size_t)blockIdx.x * NTOT + tid * 16;
    #pragma unroll
    for (int q = 0; q < 4; q++)
        *(float4*)&pp[q * 4] = make_float4(acc[q * 4], acc[q * 4 + 1],
                                           acc[q * 4 + 2], acc[q * 4 + 3]);
}

// ---------------- K4b: deterministic partial reduce ------------------------
__global__ void k_reduce_part() {
    int t = blockIdx.x * 256 + threadIdx.x;   // 0..16383
    int b = t >> 12; int n = t & 4095;
    float s = 0.0f;
    #pragma unroll 8
    for (int p = 0; p < 128; p++) s += g_part[(size_t)(b * 128 + p) * NTOT + n];
    g_d[t] = s;
}

// ---------------- K5: top-k sparsify + write output ------------------------
// 12 CTAs: blockIdx = b*3 + g.  g0: C(2048,k=8); g1: QK(1024,k=4 -> wQ,wK); g2: V(1024,k=6)
__global__ void k_topk(float* __restrict__ out) {
    int b = blockIdx.x / 3, g = blockIdx.x % 3;
    int gsize = (g == 0) ? 2048 : 1024;
    int doff = (g == 0) ? 0 : (g == 1 ? 2048 : 3072);
    int K = (g == 0) ? 8 : (g == 1 ? 4 : 6);
    __shared__ float vals[2048];
    __shared__ float rv[256];
    __shared__ int ri[256];
    __shared__ float selv[8];
    __shared__ int seli[8];
    __shared__ float ssum;
    int tid = threadIdx.x;
    for (int i = tid; i < gsize; i += 256) vals[i] = g_d[b * 4096 + doff + i];
    float* ob = out + b * 5120;
    if (g == 0)      { for (int i = tid; i < 2048; i += 256) ob[i] = 0.0f; }
    else if (g == 1) { for (int i = tid; i < 2048; i += 256) ob[2048 + i] = 0.0f; }
    else             { for (int i = tid; i < 1024; i += 256) ob[4096 + i] = 0.0f; }
    __syncthreads();

    for (int kk = 0; kk < K; kk++) {
        float bv = -1e30f; int bi = 0x7fffffff;
        for (int i = tid; i < gsize; i += 256) {
            float v = vals[i];
            if (v > bv || (v == bv && i < bi)) { bv = v; bi = i; }
        }
        rv[tid] = bv; ri[tid] = bi;
        __syncthreads();
        for (int s = 128; s; s >>= 1) {
            if (tid < s) {
                float v2 = rv[tid + s]; int i2 = ri[tid + s];
                if (v2 > rv[tid] || (v2 == rv[tid] && i2 < ri[tid])) { rv[tid] = v2; ri[tid] = i2; }
            }
            __syncthreads();
        }
        if (tid == 0) { selv[kk] = rv[0]; seli[kk] = ri[0]; vals[ri[0]] = -1e30f; }
        __syncthreads();
    }
    if (tid == 0) {
        float s = 0.0f;
        for (int kk = 0; kk < K; kk++) s += selv[kk];
        ssum = 1.0f / (s + 1e-8f);
    }
    __syncthreads();
    if (tid < K) {
        float wv = selv[tid] * ssum;
        int idx = seli[tid];
        if (g == 0) ob[idx] = wv;
        else if (g == 1) { ob[2048 + idx] = wv; ob[3072 + idx] = wv; }
        else ob[4096 + idx] = wv;
    }
}

// ---------------------------------------------------------------------------
extern "C" void kernel_launch(void* const* d_in, const int* in_sizes, int n_in,
                              void* d_out, int out_size) {
    const float *x = nullptr, *imp = nullptr, *W = nullptr, *bias = nullptr, *emb = nullptr;
    for (int i = 0; i < n_in; i++) {
        switch (in_sizes[i]) {
            case 33554432: x    = (const float*)d_in[i]; break;  // 4*4096*2048
            case 16384:    imp  = (const float*)d_in[i]; break;  // 4*4096
            case 131072:   W    = (const float*)d_in[i]; break;  // 2048*64
            case 64:       bias = (const float*)d_in[i]; break;  // 64
            case 262144:   emb  = (const float*)d_in[i]; break;  // 4096*64
            default: break;
        }
    }
    k_norm_emb<<<512, 256>>>(emb);
    k_gemm1<<<256, 256>>>(x, W, bias);
    k_gemm2<<<dim3(32, 256), 256>>>();
    k_softmax<<<512, 256>>>(imp);
    k_reduce_part<<<64, 256>>>();
    k_topk<<<12, 256>>>((float*)d_out);
}

// round 3
// speedup vs baseline: 1.5512x; 1.5512x over previous
#include <cuda_runtime.h>
#include <cuda_fp16.h>
#include <cuda_bf16.h>
#include <cstdint>

#define ROWS_TOTAL 16384
#define DIM 2048
#define NTOT 4096

// ---------------- device scratch (static; no runtime alloc) ----------------
__device__ __align__(16) __nv_bfloat16 g_Ehi[NTOT * 64];
__device__ __align__(16) __nv_bfloat16 g_Elo[NTOT * 64];
__device__ __align__(16) __nv_bfloat16 g_Whi[64 * DIM];
__device__ __align__(16) __nv_bfloat16 g_Wlo[64 * DIM];
__device__ __align__(16) __nv_bfloat16 g_Hhi[(size_t)ROWS_TOTAL * 64];
__device__ __align__(16) __nv_bfloat16 g_Hlo[(size_t)ROWS_TOTAL * 64];
__device__ __align__(16) __half g_logitsH[(size_t)ROWS_TOTAL * NTOT];  // 134 MB
__device__ __align__(16) float g_part[512 * NTOT];
__device__ float g_d[4 * NTOT];

// ---------------- helpers ----------------
__device__ __forceinline__ uint32_t smem_u32(const void* p) {
    uint32_t a;
    asm("{ .reg .u64 t; cvta.to.shared.u64 t, %1; cvt.u32.u64 %0, t; }" : "=r"(a) : "l"(p));
    return a;
}
#define SW128(o) ((o) ^ (((o) >> 3) & 0x70))

__device__ __forceinline__ void ldsm4(uint32_t addr, uint32_t& r0, uint32_t& r1,
                                      uint32_t& r2, uint32_t& r3) {
    asm volatile("ldmatrix.sync.aligned.m8n8.x4.shared.b16 {%0,%1,%2,%3}, [%4];"
                 : "=r"(r0), "=r"(r1), "=r"(r2), "=r"(r3) : "r"(addr));
}
__device__ __forceinline__ void mma_bf16(float* c, const uint32_t* a, const uint32_t* b) {
    asm volatile(
        "mma.sync.aligned.m16n8k16.row.col.f32.bf16.bf16.f32 "
        "{%0,%1,%2,%3}, {%4,%5,%6,%7}, {%8,%9}, {%0,%1,%2,%3};"
        : "+f"(c[0]), "+f"(c[1]), "+f"(c[2]), "+f"(c[3])
        : "r"(a[0]), "r"(a[1]), "r"(a[2]), "r"(a[3]), "r"(b[0]), "r"(b[1]));
}

__device__ __forceinline__ uint32_t split_pack_hi(float a, float b, uint32_t& lo) {
    __nv_bfloat162 h = __floats2bfloat162_rn(a, b);
    float ra = a - __bfloat162float(h.x);
    float rb = b - __bfloat162float(h.y);
    __nv_bfloat162 l = __floats2bfloat162_rn(ra, rb);
    lo = *reinterpret_cast<uint32_t*>(&l);
    return *reinterpret_cast<uint32_t*>(&h);
}

// fast exp (FFMA-only, avoids MUFU bottleneck)
__device__ __forceinline__ float fexp(float x) {
    x = fmaxf(x, -87.0f);
    float y = x * 1.4426950408889634f;
    float n = rintf(y);
    float t = (y - n) * 0.6931471805599453f;
    float p = fmaf(t, 8.3333333e-3f, 4.1666667e-2f);
    p = fmaf(p, t, 0.16666667f);
    p = fmaf(p, t, 0.5f);
    p = fmaf(p, t, 1.0f);
    p = fmaf(p, t, 1.0f);
    int e = (int)n;
    float s = __int_as_float((e + 127) << 23);
    return p * s;
}

// ---------------- prep kernels ----------------
__global__ void k_norm_emb(const float* __restrict__ emb) {
    int n = blockIdx.x * 8 + (threadIdx.x >> 5);
    int lane = threadIdx.x & 31;
    float v0 = emb[n * 64 + lane];
    float v1 = emb[n * 64 + lane + 32];
    float ss = v0 * v0 + v1 * v1;
    #pragma unroll
    for (int o = 16; o; o >>= 1) ss += __shfl_xor_sync(0xffffffffu, ss, o);
    float inv = rsqrtf(ss);
    float e0 = v0 * inv, e1 = v1 * inv;
    __nv_bfloat16 h0 = __float2bfloat16_rn(e0);
    __nv_bfloat16 h1 = __float2bfloat16_rn(e1);
    g_Ehi[n * 64 + lane] = h0;
    g_Ehi[n * 64 + lane + 32] = h1;
    g_Elo[n * 64 + lane] = __float2bfloat16_rn(e0 - __bfloat162float(h0));
    g_Elo[n * 64 + lane + 32] = __float2bfloat16_rn(e1 - __bfloat162float(h1));
}

__global__ void k_prep_w(const float* __restrict__ W) {
    int t = blockIdx.x * 256 + threadIdx.x;   // t = k*64 + n
    if (t >= DIM * 64) return;
    int k = t >> 6, n = t & 63;
    float v = W[t];
    __nv_bfloat16 h = __float2bfloat16_rn(v);
    g_Whi[n * DIM + k] = h;
    g_Wlo[n * DIM + k] = __float2bfloat16_rn(v - __bfloat162float(h));
}

// ---------------- GEMM1: h = x @ W + b  (mma.sync, split bf16) -------------
// CTA: 128 rows x 64 cols, 256 threads (8 warps x 16 rows). K=2048 in 64-chunks,
// double-buffered SMEM, loads for chunk c+1 issued before MMA of chunk c.
#define G1_SMEM 98304
__global__ void __launch_bounds__(256) k_gemm1_mma(const float* __restrict__ X,
                                                   const float* __restrict__ bias) {
    extern __shared__ char smem[];
    uint32_t sb = smem_u32(smem);
    int tid = threadIdx.x, wid = tid >> 5, lane = tid & 31;
    int rowbase = blockIdx.x * 128;
    const uint32_t XHI = 0, XLO = 16384, WHI = 32768, WLO = 40960, BUF = 49152;

    float acc[8][4] = {};

    int a_row = lane & 15;
    int a_kadd = (lane >> 4) << 3;
    int b_row = ((lane >> 4) << 3) + (lane & 7);
    int b_kadd = lane & 8;

    auto load_chunk = [&](int c) {
        int kb = c * 64; int b = c & 1;
        #pragma unroll
        for (int u = 0; u < 8; u++) {
            int f = tid + u * 256;                 // 0..2047
            int row = f >> 4, kq = f & 15;
            float4 v = *(const float4*)&X[(size_t)(rowbase + row) * DIM + kb + kq * 4];
            uint32_t l0, l1;
            uint32_t h0 = split_pack_hi(v.x, v.y, l0);
            uint32_t h1 = split_pack_hi(v.z, v.w, l1);
            uint32_t off = SW128((uint32_t)(row * 128 + kq * 8));
            *(uint2*)(smem + XHI + b * BUF + off) = make_uint2(h0, h1);
            *(uint2*)(smem + XLO + b * BUF + off) = make_uint2(l0, l1);
        }
        #pragma unroll
        for (int u = 0; u < 2; u++) {
            int f = tid + u * 256;                 // 0..511
            int n = f >> 3, cq = f & 7;
            uint32_t off = SW128((uint32_t)(n * 128 + cq * 16));
            *(uint4*)(smem + WHI + b * BUF + off) = *(const uint4*)&g_Whi[n * DIM + kb + cq * 8];
            *(uint4*)(smem + WLO + b * BUF + off) = *(const uint4*)&g_Wlo[n * DIM + kb + cq * 8];
        }
    };

    load_chunk(0);
    __syncthreads();
    for (int c = 0; c < 32; c++) {
        if (c + 1 < 32) load_chunk(c + 1);
        int b = c & 1;
        uint32_t xh = sb + XHI + b * BUF, xl = sb + XLO + b * BUF;
        uint32_t wh = sb + WHI + b * BUF, wl = sb + WLO + b * BUF;
        int mbase = wid * 16;
        #pragma unroll
        for (int ks = 0; ks < 4; ks++) {
            int k0 = ks * 16;
            uint32_t ahi[4], alo[4];
            uint32_t aoff = SW128((uint32_t)((mbase + a_row) * 128 + (k0 + a_kadd) * 2));
            ldsm4(xh + aoff, ahi[0], ahi[1], ahi[2], ahi[3]);
            ldsm4(xl + aoff, alo[0], alo[1], alo[2], alo[3]);
            #pragma unroll
            for (int np = 0; np < 4; np++) {
                uint32_t boff = SW128((uint32_t)((np * 16 + b_row) * 128 + (k0 + b_kadd) * 2));
                uint32_t bh[4], bl[4];
                ldsm4(wh + boff, bh[0], bh[1], bh[2], bh[3]);
                ldsm4(wl + boff, bl[0], bl[1], bl[2], bl[3]);
                mma_bf16(acc[np * 2],     ahi, bh);
                mma_bf16(acc[np * 2],     ahi, bl);
                mma_bf16(acc[np * 2],     alo, bh);
                mma_bf16(acc[np * 2 + 1], ahi, bh + 2);
                mma_bf16(acc[np * 2 + 1], ahi, bl + 2);
                mma_bf16(acc[np * 2 + 1], alo, bh + 2);
            }
        }
        __syncthreads();
    }

    // epilogue: add bias, split to bf16 hi/lo, store h
    int r0 = rowbase + wid * 16 + (lane >> 2);
    int cb = (lane & 3) * 2;
    #pragma unroll
    for (int half = 0; half < 2; half++) {
        int row = r0 + half * 8;
        size_t ro = (size_t)row * 64;
        #pragma unroll
        for (int nt = 0; nt < 8; nt++) {
            int col = nt * 8 + cb;
            float f0 = acc[nt][half * 2 + 0] + bias[col];
            float f1 = acc[nt][half * 2 + 1] + bias[col + 1];
            uint32_t lo;
            uint32_t hi = split_pack_hi(f0, f1, lo);
            *(uint32_t*)&g_Hhi[ro + col] = hi;
            *(uint32_t*)&g_Hlo[ro + col] = lo;
        }
    }
}

// ---------------- GEMM2: logits = H @ embn^T (mma.sync, split bf16) --------
// CTA: 128 rows x 128 neurons, 256 threads (warps 4x2: 32 rows x 64 cols).
// K=64 staged once. Writes logits as fp16.
#define G2_SMEM 65536
__global__ void __launch_bounds__(256) k_gemm2_mma() {
    extern __shared__ char smem[];
    uint32_t sb = smem_u32(smem);
    int tid = threadIdx.x, wid = tid >> 5, lane = tid & 31;
    int nbase = blockIdx.x * 128, rowbase = blockIdx.y * 128;
    const uint32_t AHI = 0, ALO = 16384, BHI = 32768, BLO = 49152;

    #pragma unroll
    for (int u = 0; u < 4; u++) {
        int f = tid + u * 256;                     // 0..1023
        int row = f >> 3, cq = f & 7;
        uint32_t off = SW128((uint32_t)(row * 128 + cq * 16));
        *(uint4*)(smem + AHI + off) = *(const uint4*)&g_Hhi[(size_t)(rowbase + row) * 64 + cq * 8];
        *(uint4*)(smem + ALO + off) = *(const uint4*)&g_Hlo[(size_t)(rowbase + row) * 64 + cq * 8];
    }
    #pragma unroll
    for (int u = 0; u < 4; u++) {
        int f = tid + u * 256;
        int n = f >> 3, cq = f & 7;
        uint32_t off = SW128((uint32_t)(n * 128 + cq * 16));
        *(uint4*)(smem + BHI + off) = *(const uint4*)&g_Ehi[(size_t)(nbase + n) * 64 + cq * 8];
        *(uint4*)(smem + BLO + off) = *(const uint4*)&g_Elo[(size_t)(nbase + n) * 64 + cq * 8];
    }
    __syncthreads();

    int warp_m = wid & 3, warp_n = wid >> 2;
    int mbase = warp_m * 32, nb0 = warp_n * 64;
    float acc[2][8][4] = {};
    int a_row = lane & 15;
    int a_kadd = (lane >> 4) << 3;
    int b_row = ((lane >> 4) << 3) + (lane & 7);
    int b_kadd = lane & 8;

    #pragma unroll
    for (int ks = 0; ks < 4; ks++) {
        int k0 = ks * 16;
        uint32_t ahi[2][4], alo[2][4];
        #pragma unroll
        for (int mt = 0; mt < 2; mt++) {
            uint32_t aoff = SW128((uint32_t)((mbase + mt * 16 + a_row) * 128 + (k0 + a_kadd) * 2));
            ldsm4(sb + AHI + aoff, ahi[mt][0], ahi[mt][1], ahi[mt][2], ahi[mt][3]);
            ldsm4(sb + ALO + aoff, alo[mt][0], alo[mt][1], alo[mt][2], alo[mt][3]);
        }
        #pragma unroll
        for (int np = 0; np < 4; np++) {
            uint32_t boff = SW128((uint32_t)((nb0 + np * 16 + b_row) * 128 + (k0 + b_kadd) * 2));
            uint32_t bh[4], bl[4];
            ldsm4(sb + BHI + boff, bh[0], bh[1], bh[2], bh[3]);
            ldsm4(sb + BLO + boff, bl[0], bl[1], bl[2], bl[3]);
            #pragma unroll
            for (int mt = 0; mt < 2; mt++) {
                mma_bf16(acc[mt][np * 2],     ahi[mt], bh);
                mma_bf16(acc[mt][np * 2],     ahi[mt], bl);
                mma_bf16(acc[mt][np * 2],     alo[mt], bh);
                mma_bf16(acc[mt][np * 2 + 1], ahi[mt], bh + 2);
                mma_bf16(acc[mt][np * 2 + 1], ahi[mt], bl + 2);
                mma_bf16(acc[mt][np * 2 + 1], alo[mt], bh + 2);
            }
        }
    }

    // epilogue: fp16 logits
    int cb = (lane & 3) * 2;
    #pragma unroll
    for (int mt = 0; mt < 2; mt++) {
        int r0 = rowbase + mbase + mt * 16 + (lane >> 2);
        #pragma unroll
        for (int half = 0; half < 2; half++) {
            __half* lp = g_logitsH + (size_t)(r0 + half * 8) * NTOT + nbase + nb0;
            #pragma unroll
            for (int nt = 0; nt < 8; nt++) {
                int col = nt * 8 + cb;
                __half2 h = __floats2half2_rn(acc[mt][nt][half * 2], acc[mt][nt][half * 2 + 1]);
                *(__half2*)(lp + col) = h;
            }
        }
    }
}

// ------- softmax + importance-weighted accumulate (fp16 logits) ------------
__global__ void k_softmax(const float* __restrict__ imp) {
    int tid = threadIdx.x;
    int lane = tid & 31, wid = tid >> 5;
    int rb = blockIdx.x * 32;
    __shared__ float wred[8];
    float acc[16] = {};
    int grp = (tid < 128) ? 0 : (tid < 192 ? 1 : 2);

    for (int ri = 0; ri < 32; ri++) {
        int r = rb + ri;
        const uint4* lp = (const uint4*)(g_logitsH + (size_t)r * NTOT + tid * 16);
        uint4 v0 = lp[0];
        uint4 v1 = lp[1];
        float lg[16];
        {
            const uint32_t w[8] = {v0.x, v0.y, v0.z, v0.w, v1.x, v1.y, v1.z, v1.w};
            #pragma unroll
            for (int q = 0; q < 8; q++) {
                __half2 h = *reinterpret_cast<const __half2*>(&w[q]);
                float2 f = __half22float2(h);
                lg[q * 2] = f.x; lg[q * 2 + 1] = f.y;
            }
        }
        float m = -1e30f;
        #pragma unroll
        for (int j = 0; j < 16; j++) m = fmaxf(m, lg[j]);
        #pragma unroll
        for (int o = 16; o; o >>= 1) m = fmaxf(m, __shfl_xor_sync(0xffffffffu, m, o));
        if (lane == 0) wred[wid] = m;
        __syncthreads();
        float gm;
        if (grp == 0) gm = fmaxf(fmaxf(wred[0], wred[1]), fmaxf(wred[2], wred[3]));
        else if (grp == 1) gm = fmaxf(wred[4], wred[5]);
        else gm = fmaxf(wred[6], wred[7]);
        __syncthreads();
        float e[16]; float se = 0.0f;
        #pragma unroll
        for (int j = 0; j < 16; j++) { e[j] = fexp(lg[j] - gm); se += e[j]; }
        #pragma unroll
        for (int o = 16; o; o >>= 1) se += __shfl_xor_sync(0xffffffffu, se, o);
        if (lane == 0) wred[wid] = se;
        __syncthreads();
        float gs;
        if (grp == 0) gs = (wred[0] + wred[1]) + (wred[2] + wred[3]);
        else if (grp == 1) gs = wred[4] + wred[5];
        else gs = wred[6] + wred[7];
        __syncthreads();
        float sc = imp[r] / gs;
        #pragma unroll
        for (int j = 0; j < 16; j++) acc[j] = fmaf(e[j], sc, acc[j]);
    }
    float* pp = g_part + (size_t)blockIdx.x * NTOT + tid * 16;
    #pragma unroll
    for (int q = 0; q < 4; q++)
        *(float4*)&pp[q * 4] = make_float4(acc[q * 4], acc[q * 4 + 1],
                                           acc[q * 4 + 2], acc[q * 4 + 3]);
}

__global__ void k_reduce_part() {
    int t = blockIdx.x * 256 + threadIdx.x;
    int b = t >> 12; int n = t & 4095;
    float s = 0.0f;
    #pragma unroll 8
    for (int p = 0; p < 128; p++) s += g_part[(size_t)(b * 128 + p) * NTOT + n];
    g_d[t] = s;
}

// ---------------- top-k sparsify + output ----------------------------------
__global__ void k_topk(float* __restrict__ out) {
    int b = blockIdx.x / 3, g = blockIdx.x % 3;
    int gsize = (g == 0) ? 2048 : 1024;
    int doff = (g == 0) ? 0 : (g == 1 ? 2048 : 3072);
    int K = (g == 0) ? 8 : (g == 1 ? 4 : 6);
    __shared__ float vals[2048];
    __shared__ float rv[256];
    __shared__ int ri[256];
    __shared__ float selv[8];
    __shared__ int seli[8];
    __shared__ float ssum;
    int tid = threadIdx.x;
    for (int i = tid; i < gsize; i += 256) vals[i] = g_d[b * 4096 + doff + i];
    float* ob = out + b * 5120;
    if (g == 0)      { for (int i = tid; i < 2048; i += 256) ob[i] = 0.0f; }
    else if (g == 1) { for (int i = tid; i < 2048; i += 256) ob[2048 + i] = 0.0f; }
    else             { for (int i = tid; i < 1024; i += 256) ob[4096 + i] = 0.0f; }
    __syncthreads();

    for (int kk = 0; kk < K; kk++) {
        float bv = -1e30f; int bi = 0x7fffffff;
        for (int i = tid; i < gsize; i += 256) {
            float v = vals[i];
            if (v > bv || (v == bv && i < bi)) { bv = v; bi = i; }
        }
        rv[tid] = bv; ri[tid] = bi;
        __syncthreads();
        for (int s = 128; s; s >>= 1) {
            if (tid < s) {
                float v2 = rv[tid + s]; int i2 = ri[tid + s];
                if (v2 > rv[tid] || (v2 == rv[tid] && i2 < ri[tid])) { rv[tid] = v2; ri[tid] = i2; }
            }
            __syncthreads();
        }
        if (tid == 0) { selv[kk] = rv[0]; seli[kk] = ri[0]; vals[ri[0]] = -1e30f; }
        __syncthreads();
    }
    if (tid == 0) {
        float s = 0.0f;
        for (int kk = 0; kk < K; kk++) s += selv[kk];
        ssum = 1.0f / (s + 1e-8f);
    }
    __syncthreads();
    if (tid < K) {
        float wv = selv[tid] * ssum;
        int idx = seli[tid];
        if (g == 0) ob[idx] = wv;
        else if (g == 1) { ob[2048 + idx] = wv; ob[3072 + idx] = wv; }
        else ob[4096 + idx] = wv;
    }
}

// ---------------------------------------------------------------------------
extern "C" void kernel_launch(void* const* d_in, const int* in_sizes, int n_in,
                              void* d_out, int out_size) {
    const float *x = nullptr, *imp = nullptr, *W = nullptr, *bias = nullptr, *emb = nullptr;
    for (int i = 0; i < n_in; i++) {
        switch (in_sizes[i]) {
            case 33554432: x    = (const float*)d_in[i]; break;  // 4*4096*2048
            case 16384:    imp  = (const float*)d_in[i]; break;  // 4*4096
            case 131072:   W    = (const float*)d_in[i]; break;  // 2048*64
            case 64:       bias = (const float*)d_in[i]; break;  // 64
            case 262144:   emb  = (const float*)d_in[i]; break;  // 4096*64
            default: break;
        }
    }
    static bool attr_done = false;
    if (!attr_done) {
        cudaFuncSetAttribute(k_gemm1_mma, cudaFuncAttributeMaxDynamicSharedMemorySize, G1_SMEM);
        cudaFuncSetAttribute(k_gemm2_mma, cudaFuncAttributeMaxDynamicSharedMemorySize, G2_SMEM);
        attr_done = true;
    }

    k_norm_emb<<<512, 256>>>(emb);
    k_prep_w<<<512, 256>>>(W);
    k_gemm1_mma<<<128, 256, G1_SMEM>>>(x, bias);
    k_gemm2_mma<<<dim3(32, 128), 256, G2_SMEM>>>();
    k_softmax<<<512, 256>>>(imp);
    k_reduce_part<<<64, 256>>>();
    k_topk<<<12, 256>>>((float*)d_out);
}

// round 4
// speedup vs baseline: 1.9702x; 1.2701x over previous
#include <cuda_runtime.h>
#include <cuda_fp16.h>
#include <cuda_bf16.h>
#include <cstdint>

#define ROWS_TOTAL 16384
#define DIM 2048
#define NTOT 4096

// ---------------- device scratch (static; no runtime alloc) ----------------
__device__ __align__(16) __nv_bfloat16 g_Ehi[NTOT * 64];
__device__ __align__(16) __nv_bfloat16 g_Elo[NTOT * 64];
__device__ __align__(16) __nv_bfloat16 g_Whi[64 * DIM];
__device__ __align__(16) __nv_bfloat16 g_Wlo[64 * DIM];
__device__ __align__(16) __nv_bfloat16 g_Hhi[(size_t)ROWS_TOTAL * 64];
__device__ __align__(16) __nv_bfloat16 g_Hlo[(size_t)ROWS_TOTAL * 64];
__device__ __align__(16) __half g_logitsH[(size_t)ROWS_TOTAL * NTOT];  // 134 MB
__device__ __align__(16) float g_part[512 * NTOT];
__device__ float g_d[4 * NTOT];

// ---------------- helpers ----------------
__device__ __forceinline__ uint32_t smem_u32(const void* p) {
    uint32_t a;
    asm("{ .reg .u64 t; cvta.to.shared.u64 t, %1; cvt.u32.u64 %0, t; }" : "=r"(a) : "l"(p));
    return a;
}
#define SW128(o) ((o) ^ (((o) >> 3) & 0x70))

__device__ __forceinline__ void ldsm4(uint32_t addr, uint32_t& r0, uint32_t& r1,
                                      uint32_t& r2, uint32_t& r3) {
    asm volatile("ldmatrix.sync.aligned.m8n8.x4.shared.b16 {%0,%1,%2,%3}, [%4];"
                 : "=r"(r0), "=r"(r1), "=r"(r2), "=r"(r3) : "r"(addr));
}
__device__ __forceinline__ void mma_bf16(float* c, const uint32_t* a, const uint32_t* b) {
    asm volatile(
        "mma.sync.aligned.m16n8k16.row.col.f32.bf16.bf16.f32 "
        "{%0,%1,%2,%3}, {%4,%5,%6,%7}, {%8,%9}, {%0,%1,%2,%3};"
        : "+f"(c[0]), "+f"(c[1]), "+f"(c[2]), "+f"(c[3])
        : "r"(a[0]), "r"(a[1]), "r"(a[2]), "r"(a[3]), "r"(b[0]), "r"(b[1]));
}

__device__ __forceinline__ uint32_t split_pack_hi(float a, float b, uint32_t& lo) {
    __nv_bfloat162 h = __floats2bfloat162_rn(a, b);
    float ra = a - __bfloat162float(h.x);
    float rb = b - __bfloat162float(h.y);
    __nv_bfloat162 l = __floats2bfloat162_rn(ra, rb);
    lo = *reinterpret_cast<uint32_t*>(&l);
    return *reinterpret_cast<uint32_t*>(&h);
}

// fast exp (FFMA-only, avoids MUFU bottleneck)
__device__ __forceinline__ float fexp(float x) {
    x = fmaxf(x, -87.0f);
    float y = x * 1.4426950408889634f;
    float n = rintf(y);
    float t = (y - n) * 0.6931471805599453f;
    float p = fmaf(t, 8.3333333e-3f, 4.1666667e-2f);
    p = fmaf(p, t, 0.16666667f);
    p = fmaf(p, t, 0.5f);
    p = fmaf(p, t, 1.0f);
    p = fmaf(p, t, 1.0f);
    int e = (int)n;
    float s = __int_as_float((e + 127) << 23);
    return p * s;
}

// ---------------- prep kernels ----------------
__global__ void k_norm_emb(const float* __restrict__ emb) {
    int n = blockIdx.x * 8 + (threadIdx.x >> 5);
    int lane = threadIdx.x & 31;
    float v0 = emb[n * 64 + lane];
    float v1 = emb[n * 64 + lane + 32];
    float ss = v0 * v0 + v1 * v1;
    #pragma unroll
    for (int o = 16; o; o >>= 1) ss += __shfl_xor_sync(0xffffffffu, ss, o);
    float inv = rsqrtf(ss);
    float e0 = v0 * inv, e1 = v1 * inv;
    __nv_bfloat16 h0 = __float2bfloat16_rn(e0);
    __nv_bfloat16 h1 = __float2bfloat16_rn(e1);
    g_Ehi[n * 64 + lane] = h0;
    g_Ehi[n * 64 + lane + 32] = h1;
    g_Elo[n * 64 + lane] = __float2bfloat16_rn(e0 - __bfloat162float(h0));
    g_Elo[n * 64 + lane + 32] = __float2bfloat16_rn(e1 - __bfloat162float(h1));
}

__global__ void k_prep_w(const float* __restrict__ W) {
    int t = blockIdx.x * 256 + threadIdx.x;   // t = k*64 + n
    if (t >= DIM * 64) return;
    int k = t >> 6, n = t & 63;
    float v = W[t];
    __nv_bfloat16 h = __float2bfloat16_rn(v);
    g_Whi[n * DIM + k] = h;
    g_Wlo[n * DIM + k] = __float2bfloat16_rn(v - __bfloat162float(h));
}

// ---------------- GEMM1: h = x @ W + b  (mma.sync, split bf16) -------------
// CTA: 128 rows x 64 cols, 256 threads. K=2048 in 64-chunks, double-buffered.
// Pipeline: LDG(c+1)->regs ; MMA(c) ; convert+STS(c+1) ; sync.
#define G1_SMEM 98304
__global__ void __launch_bounds__(256) k_gemm1_mma(const float* __restrict__ X,
                                                   const float* __restrict__ bias) {
    extern __shared__ char smem[];
    uint32_t sb = smem_u32(smem);
    int tid = threadIdx.x, wid = tid >> 5, lane = tid & 31;
    int rowbase = blockIdx.x * 128;
    const uint32_t XHI = 0, XLO = 16384, WHI = 32768, WLO = 40960, BUF = 49152;

    float acc[8][4] = {};
    float4 xv[8];
    uint4 wv[4];

    int a_row = lane & 15;
    int a_kadd = (lane >> 4) << 3;
    int b_row = ((lane >> 4) << 3) + (lane & 7);
    int b_kadd = lane & 8;

    auto ldg_chunk = [&](int c) {
        int kb = c * 64;
        #pragma unroll
        for (int u = 0; u < 8; u++) {
            int f = tid + u * 256;
            int row = f >> 4, kq = f & 15;
            xv[u] = *(const float4*)&X[(size_t)(rowbase + row) * DIM + kb + kq * 4];
        }
        #pragma unroll
        for (int u = 0; u < 2; u++) {
            int f = tid + u * 256;
            int n = f >> 3, cq = f & 7;
            wv[u * 2]     = *(const uint4*)&g_Whi[n * DIM + kb + cq * 8];
            wv[u * 2 + 1] = *(const uint4*)&g_Wlo[n * DIM + kb + cq * 8];
        }
    };
    auto sts_chunk = [&](int c) {
        int b = c & 1;
        #pragma unroll
        for (int u = 0; u < 8; u++) {
            int f = tid + u * 256;
            int row = f >> 4, kq = f & 15;
            uint32_t l0, l1;
            uint32_t h0 = split_pack_hi(xv[u].x, xv[u].y, l0);
            uint32_t h1 = split_pack_hi(xv[u].z, xv[u].w, l1);
            uint32_t off = SW128((uint32_t)(row * 128 + kq * 8));
            *(uint2*)(smem + XHI + b * BUF + off) = make_uint2(h0, h1);
            *(uint2*)(smem + XLO + b * BUF + off) = make_uint2(l0, l1);
        }
        #pragma unroll
        for (int u = 0; u < 2; u++) {
            int f = tid + u * 256;
            int n = f >> 3, cq = f & 7;
            uint32_t off = SW128((uint32_t)(n * 128 + cq * 16));
            *(uint4*)(smem + WHI + b * BUF + off) = wv[u * 2];
            *(uint4*)(smem + WLO + b * BUF + off) = wv[u * 2 + 1];
        }
    };

    ldg_chunk(0);
    sts_chunk(0);
    __syncthreads();
    for (int c = 0; c < 32; c++) {
        if (c + 1 < 32) ldg_chunk(c + 1);          // LDG latency hides under MMA
        int b = c & 1;
        uint32_t xh = sb + XHI + b * BUF, xl = sb + XLO + b * BUF;
        uint32_t wh = sb + WHI + b * BUF, wl = sb + WLO + b * BUF;
        int mbase = wid * 16;
        #pragma unroll
        for (int ks = 0; ks < 4; ks++) {
            int k0 = ks * 16;
            uint32_t ahi[4], alo[4];
            uint32_t aoff = SW128((uint32_t)((mbase + a_row) * 128 + (k0 + a_kadd) * 2));
            ldsm4(xh + aoff, ahi[0], ahi[1], ahi[2], ahi[3]);
            ldsm4(xl + aoff, alo[0], alo[1], alo[2], alo[3]);
            #pragma unroll
            for (int np = 0; np < 4; np++) {
                uint32_t boff = SW128((uint32_t)((np * 16 + b_row) * 128 + (k0 + b_kadd) * 2));
                uint32_t bh[4], bl[4];
                ldsm4(wh + boff, bh[0], bh[1], bh[2], bh[3]);
                ldsm4(wl + boff, bl[0], bl[1], bl[2], bl[3]);
                mma_bf16(acc[np * 2],     ahi, bh);
                mma_bf16(acc[np * 2],     ahi, bl);
                mma_bf16(acc[np * 2],     alo, bh);
                mma_bf16(acc[np * 2 + 1], ahi, bh + 2);
                mma_bf16(acc[np * 2 + 1], ahi, bl + 2);
                mma_bf16(acc[np * 2 + 1], alo, bh + 2);
            }
        }
        if (c + 1 < 32) sts_chunk(c + 1);
        __syncthreads();
    }

    // epilogue: add bias, split to bf16 hi/lo, store h
    int r0 = rowbase + wid * 16 + (lane >> 2);
    int cb = (lane & 3) * 2;
    #pragma unroll
    for (int half = 0; half < 2; half++) {
        int row = r0 + half * 8;
        size_t ro = (size_t)row * 64;
        #pragma unroll
        for (int nt = 0; nt < 8; nt++) {
            int col = nt * 8 + cb;
            float f0 = acc[nt][half * 2 + 0] + bias[col];
            float f1 = acc[nt][half * 2 + 1] + bias[col + 1];
            uint32_t lo;
            uint32_t hi = split_pack_hi(f0, f1, lo);
            *(uint32_t*)&g_Hhi[ro + col] = hi;
            *(uint32_t*)&g_Hlo[ro + col] = lo;
        }
    }
}

// ---------------- GEMM2: logits = H @ embn^T (mma.sync, split bf16) --------
// grid (32 n-tiles, 32 row-groups). Each CTA keeps B (128n x 64k hi/lo) resident
// and loops over 4 row-tiles of 128 rows, prefetching next A tile into regs.
#define G2_SMEM 98304
__global__ void __launch_bounds__(256) k_gemm2_mma() {
    extern __shared__ char smem[];
    uint32_t sb = smem_u32(smem);
    int tid = threadIdx.x, wid = tid >> 5, lane = tid & 31;
    int nbase = blockIdx.x * 128;
    int rowgrp = blockIdx.y * 512;
    // layout: A buf0 hi/lo @0/16384, A buf1 hi/lo @32768/49152, B hi/lo @65536/81920
    const uint32_t ABUF = 32768, BHI = 65536, BLO = 81920;

    // B resident load (once)
    #pragma unroll
    for (int u = 0; u < 4; u++) {
        int f = tid + u * 256;                  // 0..1023
        int n = f >> 3, cq = f & 7;
        uint32_t off = SW128((uint32_t)(n * 128 + cq * 16));
        *(uint4*)(smem + BHI + off) = *(const uint4*)&g_Ehi[(size_t)(nbase + n) * 64 + cq * 8];
        *(uint4*)(smem + BLO + off) = *(const uint4*)&g_Elo[(size_t)(nbase + n) * 64 + cq * 8];
    }

    uint4 av[8];                                 // prefetch regs: 4 hi + 4 lo
    auto ldg_a = [&](int rt) {
        int rowbase = rowgrp + rt * 128;
        #pragma unroll
        for (int u = 0; u < 4; u++) {
            int f = tid + u * 256;
            int row = f >> 3, cq = f & 7;
            av[u]     = *(const uint4*)&g_Hhi[(size_t)(rowbase + row) * 64 + cq * 8];
            av[u + 4] = *(const uint4*)&g_Hlo[(size_t)(rowbase + row) * 64 + cq * 8];
        }
    };
    auto sts_a = [&](int rt) {
        int b = rt & 1;
        #pragma unroll
        for (int u = 0; u < 4; u++) {
            int f = tid + u * 256;
            int row = f >> 3, cq = f & 7;
            uint32_t off = SW128((uint32_t)(row * 128 + cq * 16));
            *(uint4*)(smem + b * ABUF + off)         = av[u];
            *(uint4*)(smem + b * ABUF + 16384 + off) = av[u + 4];
        }
    };

    int warp_m = wid & 3, warp_n = wid >> 2;
    int mbase = warp_m * 32, nb0 = warp_n * 64;
    int a_row = lane & 15;
    int a_kadd = (lane >> 4) << 3;
    int b_row = ((lane >> 4) << 3) + (lane & 7);
    int b_kadd = lane & 8;
    int cb = (lane & 3) * 2;

    ldg_a(0);
    sts_a(0);
    __syncthreads();

    for (int rt = 0; rt < 4; rt++) {
        if (rt + 1 < 4) ldg_a(rt + 1);          // hide A LDG under MMAs
        int bsel = rt & 1;
        uint32_t ah_base = sb + bsel * ABUF;
        uint32_t al_base = ah_base + 16384;
        float acc[2][8][4] = {};

        #pragma unroll
        for (int ks = 0; ks < 4; ks++) {
            int k0 = ks * 16;
            uint32_t ahi[2][4], alo[2][4];
            #pragma unroll
            for (int mt = 0; mt < 2; mt++) {
                uint32_t aoff = SW128((uint32_t)((mbase + mt * 16 + a_row) * 128 + (k0 + a_kadd) * 2));
                ldsm4(ah_base + aoff, ahi[mt][0], ahi[mt][1], ahi[mt][2], ahi[mt][3]);
                ldsm4(al_base + aoff, alo[mt][0], alo[mt][1], alo[mt][2], alo[mt][3]);
            }
            #pragma unroll
            for (int np = 0; np < 4; np++) {
                uint32_t boff = SW128((uint32_t)((nb0 + np * 16 + b_row) * 128 + (k0 + b_kadd) * 2));
                uint32_t bh[4], bl[4];
                ldsm4(sb + BHI + boff, bh[0], bh[1], bh[2], bh[3]);
                ldsm4(sb + BLO + boff, bl[0], bl[1], bl[2], bl[3]);
                #pragma unroll
                for (int mt = 0; mt < 2; mt++) {
                    mma_bf16(acc[mt][np * 2],     ahi[mt], bh);
                    mma_bf16(acc[mt][np * 2],     ahi[mt], bl);
                    mma_bf16(acc[mt][np * 2],     alo[mt], bh);
                    mma_bf16(acc[mt][np * 2 + 1], ahi[mt], bh + 2);
                    mma_bf16(acc[mt][np * 2 + 1], ahi[mt], bl + 2);
                    mma_bf16(acc[mt][np * 2 + 1], alo[mt], bh + 2);
                }
            }
        }

        // epilogue: fp16 logits for this row tile
        int rowbase = rowgrp + rt * 128;
        #pragma unroll
        for (int mt = 0; mt < 2; mt++) {
            int r0 = rowbase + mbase + mt * 16 + (lane >> 2);
            #pragma unroll
            for (int half = 0; half < 2; half++) {
                __half* lp = g_logitsH + (size_t)(r0 + half * 8) * NTOT + nbase + nb0;
                #pragma unroll
                for (int nt = 0; nt < 8; nt++) {
                    int col = nt * 8 + cb;
                    __half2 h = __floats2half2_rn(acc[mt][nt][half * 2], acc[mt][nt][half * 2 + 1]);
                    *(__half2*)(lp + col) = h;
                }
            }
        }
        if (rt + 1 < 4) {
            __syncthreads();                     // everyone done reading buf[(rt+1)&1]
            sts_a(rt + 1);
            __syncthreads();
        }
    }
}

// ------- softmax + importance-weighted accumulate (fp16 logits) ------------
__global__ void k_softmax(const float* __restrict__ imp) {
    int tid = threadIdx.x;
    int lane = tid & 31, wid = tid >> 5;
    int rb = blockIdx.x * 32;
    __shared__ float wred[8];
    float acc[16] = {};
    int grp = (tid < 128) ? 0 : (tid < 192 ? 1 : 2);

    for (int ri = 0; ri < 32; ri++) {
        int r = rb + ri;
        const uint4* lp = (const uint4*)(g_logitsH + (size_t)r * NTOT + tid * 16);
        uint4 v0 = lp[0];
        uint4 v1 = lp[1];
        float lg[16];
        {
            const uint32_t w[8] = {v0.x, v0.y, v0.z, v0.w, v1.x, v1.y, v1.z, v1.w};
            #pragma unroll
            for (int q = 0; q < 8; q++) {
                __half2 h = *reinterpret_cast<const __half2*>(&w[q]);
                float2 f = __half22float2(h);
                lg[q * 2] = f.x; lg[q * 2 + 1] = f.y;
            }
        }
        float m = -1e30f;
        #pragma unroll
        for (int j = 0; j < 16; j++) m = fmaxf(m, lg[j]);
        #pragma unroll
        for (int o = 16; o; o >>= 1) m = fmaxf(m, __shfl_xor_sync(0xffffffffu, m, o));
        if (lane == 0) wred[wid] = m;
        __syncthreads();
        float gm;
        if (grp == 0) gm = fmaxf(fmaxf(wred[0], wred[1]), fmaxf(wred[2], wred[3]));
        else if (grp == 1) gm = fmaxf(wred[4], wred[5]);
        else gm = fmaxf(wred[6], wred[7]);
        __syncthreads();
        float e[16]; float se = 0.0f;
        #pragma unroll
        for (int j = 0; j < 16; j++) { e[j] = fexp(lg[j] - gm); se += e[j]; }
        #pragma unroll
        for (int o = 16; o; o >>= 1) se += __shfl_xor_sync(0xffffffffu, se, o);
        if (lane == 0) wred[wid] = se;
        __syncthreads();
        float gs;
        if (grp == 0) gs = (wred[0] + wred[1]) + (wred[2] + wred[3]);
        else if (grp == 1) gs = wred[4] + wred[5];
        else gs = wred[6] + wred[7];
        __syncthreads();
        float sc = imp[r] / gs;
        #pragma unroll
        for (int j = 0; j < 16; j++) acc[j] = fmaf(e[j], sc, acc[j]);
    }
    float* pp = g_part + (size_t)blockIdx.x * NTOT + tid * 16;
    #pragma unroll
    for (int q = 0; q < 4; q++)
        *(float4*)&pp[q * 4] = make_float4(acc[q * 4], acc[q * 4 + 1],
                                           acc[q * 4 + 2], acc[q * 4 + 3]);
}

__global__ void k_reduce_part() {
    int t = blockIdx.x * 256 + threadIdx.x;
    int b = t >> 12; int n = t & 4095;
    float s = 0.0f;
    #pragma unroll 8
    for (int p = 0; p < 128; p++) s += g_part[(size_t)(b * 128 + p) * NTOT + n];
    g_d[t] = s;
}

// ---------------- top-k sparsify + output ----------------------------------
__global__ void k_topk(float* __restrict__ out) {
    int b = blockIdx.x / 3, g = blockIdx.x % 3;
    int gsize = (g == 0) ? 2048 : 1024;
    int doff = (g == 0) ? 0 : (g == 1 ? 2048 : 3072);
    int K = (g == 0) ? 8 : (g == 1 ? 4 : 6);
    __shared__ float vals[2048];
    __shared__ float rv[256];
    __shared__ int ri[256];
    __shared__ float selv[8];
    __shared__ int seli[8];
    __shared__ float ssum;
    int tid = threadIdx.x;
    for (int i = tid; i < gsize; i += 256) vals[i] = g_d[b * 4096 + doff + i];
    float* ob = out + b * 5120;
    if (g == 0)      { for (int i = tid; i < 2048; i += 256) ob[i] = 0.0f; }
    else if (g == 1) { for (int i = tid; i < 2048; i += 256) ob[2048 + i] = 0.0f; }
    else             { for (int i = tid; i < 1024; i += 256) ob[4096 + i] = 0.0f; }
    __syncthreads();

    for (int kk = 0; kk < K; kk++) {
        float bv = -1e30f; int bi = 0x7fffffff;
        for (int i = tid; i < gsize; i += 256) {
            float v = vals[i];
            if (v > bv || (v == bv && i < bi)) { bv = v; bi = i; }
        }
        rv[tid] = bv; ri[tid] = bi;
        __syncthreads();
        for (int s = 128; s; s >>= 1) {
            if (tid < s) {
                float v2 = rv[tid + s]; int i2 = ri[tid + s];
                if (v2 > rv[tid] || (v2 == rv[tid] && i2 < ri[tid])) { rv[tid] = v2; ri[tid] = i2; }
            }
            __syncthreads();
        }
        if (tid == 0) { selv[kk] = rv[0]; seli[kk] = ri[0]; vals[ri[0]] = -1e30f; }
        __syncthreads();
    }
    if (tid == 0) {
        float s = 0.0f;
        for (int kk = 0; kk < K; kk++) s += selv[kk];
        ssum = 1.0f / (s + 1e-8f);
    }
    __syncthreads();
    if (tid < K) {
        float wv = selv[tid] * ssum;
        int idx = seli[tid];
        if (g == 0) ob[idx] = wv;
        else if (g == 1) { ob[2048 + idx] = wv; ob[3072 + idx] = wv; }
        else ob[4096 + idx] = wv;
    }
}

// ---------------------------------------------------------------------------
extern "C" void kernel_launch(void* const* d_in, const int* in_sizes, int n_in,
                              void* d_out, int out_size) {
    const float *x = nullptr, *imp = nullptr, *W = nullptr, *bias = nullptr, *emb = nullptr;
    for (int i = 0; i < n_in; i++) {
        switch (in_sizes[i]) {
            case 33554432: x    = (const float*)d_in[i]; break;  // 4*4096*2048
            case 16384:    imp  = (const float*)d_in[i]; break;  // 4*4096
            case 131072:   W    = (const float*)d_in[i]; break;  // 2048*64
            case 64:       bias = (const float*)d_in[i]; break;  // 64
            case 262144:   emb  = (const float*)d_in[i]; break;  // 4096*64
            default: break;
        }
    }
    cudaFuncSetAttribute(k_gemm1_mma, cudaFuncAttributeMaxDynamicSharedMemorySize, G1_SMEM);
    cudaFuncSetAttribute(k_gemm2_mma, cudaFuncAttributeMaxDynamicSharedMemorySize, G2_SMEM);

    k_norm_emb<<<512, 256>>>(emb);
    k_prep_w<<<512, 256>>>(W);
    k_gemm1_mma<<<128, 256, G1_SMEM>>>(x, bias);
    k_gemm2_mma<<<dim3(32, 32), 256, G2_SMEM>>>();
    k_softmax<<<512, 256>>>(imp);
    k_reduce_part<<<64, 256>>>();
    k_topk<<<12, 256>>>((float*)d_out);
}

// round 5
// speedup vs baseline: 2.0139x; 1.0222x over previous
#include <cuda_runtime.h>
#include <cuda_fp16.h>
#include <cuda_bf16.h>
#include <cstdint>

#define ROWS_TOTAL 16384
#define DIM 2048
#define NTOT 4096

// ---------------- device scratch (static; no runtime alloc) ----------------
__device__ __align__(16) __nv_bfloat16 g_Ehi[NTOT * 64];
__device__ __align__(16) __nv_bfloat16 g_Elo[NTOT * 64];
__device__ __align__(16) __nv_bfloat16 g_Whi[64 * DIM];
__device__ __align__(16) __nv_bfloat16 g_Wlo[64 * DIM];
__device__ __align__(16) float g_h1p[2 * (size_t)ROWS_TOTAL * 64];   // K-split partials, 8MB
__device__ __align__(16) __nv_bfloat16 g_Hhi[(size_t)ROWS_TOTAL * 64];
__device__ __align__(16) __nv_bfloat16 g_Hlo[(size_t)ROWS_TOTAL * 64];
__device__ __align__(16) __half g_logitsH[(size_t)ROWS_TOTAL * NTOT];  // 134 MB
__device__ __align__(16) float g_part[512 * NTOT];
__device__ float g_d[4 * NTOT];

// ---------------- helpers ----------------
__device__ __forceinline__ uint32_t smem_u32(const void* p) {
    uint32_t a;
    asm("{ .reg .u64 t; cvta.to.shared.u64 t, %1; cvt.u32.u64 %0, t; }" : "=r"(a) : "l"(p));
    return a;
}
#define SW128(o) ((o) ^ (((o) >> 3) & 0x70))

__device__ __forceinline__ void ldsm4(uint32_t addr, uint32_t& r0, uint32_t& r1,
                                      uint32_t& r2, uint32_t& r3) {
    asm volatile("ldmatrix.sync.aligned.m8n8.x4.shared.b16 {%0,%1,%2,%3}, [%4];"
                 : "=r"(r0), "=r"(r1), "=r"(r2), "=r"(r3) : "r"(addr));
}
__device__ __forceinline__ void mma_bf16(float* c, const uint32_t* a, const uint32_t* b) {
    asm volatile(
        "mma.sync.aligned.m16n8k16.row.col.f32.bf16.bf16.f32 "
        "{%0,%1,%2,%3}, {%4,%5,%6,%7}, {%8,%9}, {%0,%1,%2,%3};"
        : "+f"(c[0]), "+f"(c[1]), "+f"(c[2]), "+f"(c[3])
        : "r"(a[0]), "r"(a[1]), "r"(a[2]), "r"(a[3]), "r"(b[0]), "r"(b[1]));
}

__device__ __forceinline__ uint32_t split_pack_hi(float a, float b, uint32_t& lo) {
    __nv_bfloat162 h = __floats2bfloat162_rn(a, b);
    float ra = a - __bfloat162float(h.x);
    float rb = b - __bfloat162float(h.y);
    __nv_bfloat162 l = __floats2bfloat162_rn(ra, rb);
    lo = *reinterpret_cast<uint32_t*>(&l);
    return *reinterpret_cast<uint32_t*>(&h);
}

// fast exp (FFMA-only, avoids MUFU bottleneck)
__device__ __forceinline__ float fexp(float x) {
    x = fmaxf(x, -87.0f);
    float y = x * 1.4426950408889634f;
    float n = rintf(y);
    float t = (y - n) * 0.6931471805599453f;
    float p = fmaf(t, 8.3333333e-3f, 4.1666667e-2f);
    p = fmaf(p, t, 0.16666667f);
    p = fmaf(p, t, 0.5f);
    p = fmaf(p, t, 1.0f);
    p = fmaf(p, t, 1.0f);
    int e = (int)n;
    float s = __int_as_float((e + 127) << 23);
    return p * s;
}

// ---------------- prep kernels ----------------
__global__ void k_norm_emb(const float* __restrict__ emb) {
    int n = blockIdx.x * 8 + (threadIdx.x >> 5);
    int lane = threadIdx.x & 31;
    float v0 = emb[n * 64 + lane];
    float v1 = emb[n * 64 + lane + 32];
    float ss = v0 * v0 + v1 * v1;
    #pragma unroll
    for (int o = 16; o; o >>= 1) ss += __shfl_xor_sync(0xffffffffu, ss, o);
    float inv = rsqrtf(ss);
    float e0 = v0 * inv, e1 = v1 * inv;
    __nv_bfloat16 h0 = __float2bfloat16_rn(e0);
    __nv_bfloat16 h1 = __float2bfloat16_rn(e1);
    g_Ehi[n * 64 + lane] = h0;
    g_Ehi[n * 64 + lane + 32] = h1;
    g_Elo[n * 64 + lane] = __float2bfloat16_rn(e0 - __bfloat162float(h0));
    g_Elo[n * 64 + lane + 32] = __float2bfloat16_rn(e1 - __bfloat162float(h1));
}

__global__ void k_prep_w(const float* __restrict__ W) {
    int t = blockIdx.x * 256 + threadIdx.x;   // t = k*64 + n
    if (t >= DIM * 64) return;
    int k = t >> 6, n = t & 63;
    float v = W[t];
    __nv_bfloat16 h = __float2bfloat16_rn(v);
    g_Whi[n * DIM + k] = h;
    g_Wlo[n * DIM + k] = __float2bfloat16_rn(v - __bfloat162float(h));
}

// ---------------- GEMM1: h-partials = x @ W (mma.sync, split bf16) ---------
// grid (256 row-tiles, 2 K-halves). CTA: 64 rows x 64 cols, K=1024 (16 chunks),
// double-buffered; LDG(c+1) -> MMA(c) -> STS(c+1). fp32 partials to g_h1p.
#define G1_SMEM 65536
__global__ void __launch_bounds__(256, 2) k_gemm1_mma(const float* __restrict__ X) {
    extern __shared__ char smem[];
    uint32_t sb = smem_u32(smem);
    int tid = threadIdx.x, wid = tid >> 5, lane = tid & 31;
    int rowbase = blockIdx.x * 64;
    int kbase = blockIdx.y * 1024;
    const uint32_t XHI = 0, XLO = 8192, WHI = 16384, WLO = 24576, BUF = 32768;

    float acc[4][4] = {};
    float4 xv[4];
    uint4 wv[4];

    int warp_m = wid & 3, warp_n = wid >> 2;
    int mbase = warp_m * 16, nb0 = warp_n * 32;
    int a_row = lane & 15;
    int a_kadd = (lane >> 4) << 3;
    int b_row = ((lane >> 4) << 3) + (lane & 7);
    int b_kadd = lane & 8;

    auto ldg_chunk = [&](int c) {
        int kb = kbase + c * 64;
        #pragma unroll
        for (int u = 0; u < 4; u++) {
            int f = tid + u * 256;                 // 0..1023
            int row = f >> 4, kq = f & 15;
            xv[u] = *(const float4*)&X[(size_t)(rowbase + row) * DIM + kb + kq * 4];
        }
        #pragma unroll
        for (int u = 0; u < 2; u++) {
            int f = tid + u * 256;                 // 0..511
            int n = f >> 3, cq = f & 7;
            wv[u * 2]     = *(const uint4*)&g_Whi[n * DIM + kb + cq * 8];
            wv[u * 2 + 1] = *(const uint4*)&g_Wlo[n * DIM + kb + cq * 8];
        }
    };
    auto sts_chunk = [&](int c) {
        int b = c & 1;
        #pragma unroll
        for (int u = 0; u < 4; u++) {
            int f = tid + u * 256;
            int row = f >> 4, kq = f & 15;
            uint32_t l0, l1;
            uint32_t h0 = split_pack_hi(xv[u].x, xv[u].y, l0);
            uint32_t h1 = split_pack_hi(xv[u].z, xv[u].w, l1);
            uint32_t off = SW128((uint32_t)(row * 128 + kq * 8));
            *(uint2*)(smem + XHI + b * BUF + off) = make_uint2(h0, h1);
            *(uint2*)(smem + XLO + b * BUF + off) = make_uint2(l0, l1);
        }
        #pragma unroll
        for (int u = 0; u < 2; u++) {
            int f = tid + u * 256;
            int n = f >> 3, cq = f & 7;
            uint32_t off = SW128((uint32_t)(n * 128 + cq * 16));
            *(uint4*)(smem + WHI + b * BUF + off) = wv[u * 2];
            *(uint4*)(smem + WLO + b * BUF + off) = wv[u * 2 + 1];
        }
    };

    ldg_chunk(0);
    sts_chunk(0);
    __syncthreads();
    for (int c = 0; c < 16; c++) {
        if (c + 1 < 16) ldg_chunk(c + 1);
        int b = c & 1;
        uint32_t xh = sb + XHI + b * BUF, xl = sb + XLO + b * BUF;
        uint32_t wh = sb + WHI + b * BUF, wl = sb + WLO + b * BUF;
        #pragma unroll
        for (int ks = 0; ks < 4; ks++) {
            int k0 = ks * 16;
            uint32_t ahi[4], alo[4];
            uint32_t aoff = SW128((uint32_t)((mbase + a_row) * 128 + (k0 + a_kadd) * 2));
            ldsm4(xh + aoff, ahi[0], ahi[1], ahi[2], ahi[3]);
            ldsm4(xl + aoff, alo[0], alo[1], alo[2], alo[3]);
            uint32_t bh[2][4], bl[2][4];
            #pragma unroll
            for (int nh = 0; nh < 2; nh++) {
                uint32_t boff = SW128((uint32_t)((nb0 + nh * 16 + b_row) * 128 + (k0 + b_kadd) * 2));
                ldsm4(wh + boff, bh[nh][0], bh[nh][1], bh[nh][2], bh[nh][3]);
                ldsm4(wl + boff, bl[nh][0], bl[nh][1], bl[nh][2], bl[nh][3]);
            }
            // pass-ordered: same-acc MMAs are 4 apart
            #pragma unroll
            for (int nh = 0; nh < 2; nh++) {
                mma_bf16(acc[nh * 2],     ahi, bh[nh]);
                mma_bf16(acc[nh * 2 + 1], ahi, bh[nh] + 2);
            }
            #pragma unroll
            for (int nh = 0; nh < 2; nh++) {
                mma_bf16(acc[nh * 2],     ahi, bl[nh]);
                mma_bf16(acc[nh * 2 + 1], ahi, bl[nh] + 2);
            }
            #pragma unroll
            for (int nh = 0; nh < 2; nh++) {
                mma_bf16(acc[nh * 2],     alo, bh[nh]);
                mma_bf16(acc[nh * 2 + 1], alo, bh[nh] + 2);
            }
        }
        if (c + 1 < 16) sts_chunk(c + 1);
        __syncthreads();
    }

    // epilogue: fp32 partials
    float* pbase = g_h1p + (size_t)blockIdx.y * ROWS_TOTAL * 64;
    int r0 = rowbase + mbase + (lane >> 2);
    int cb = (lane & 3) * 2;
    #pragma unroll
    for (int half = 0; half < 2; half++) {
        int row = r0 + half * 8;
        #pragma unroll
        for (int nt = 0; nt < 4; nt++) {
            int col = nb0 + nt * 8 + cb;
            *(float2*)&pbase[(size_t)row * 64 + col] =
                make_float2(acc[nt][half * 2], acc[nt][half * 2 + 1]);
        }
    }
}

// ---------------- combine partials + bias -> split bf16 h ------------------
__global__ void k_combine(const float* __restrict__ bias) {
    int t = blockIdx.x * 256 + threadIdx.x;    // 0..524287, 2 cols each
    int idx = t * 2;
    int col = idx & 63;
    float2 p0 = *(const float2*)&g_h1p[idx];
    float2 p1 = *(const float2*)&g_h1p[idx + (size_t)ROWS_TOTAL * 64];
    float f0 = p0.x + p1.x + bias[col];
    float f1 = p0.y + p1.y + bias[col + 1];
    uint32_t lo;
    uint32_t hi = split_pack_hi(f0, f1, lo);
    *(uint32_t*)&g_Hhi[idx] = hi;
    *(uint32_t*)&g_Hlo[idx] = lo;
}

// ---------------- GEMM2: logits = H @ embn^T (mma.sync, split bf16) --------
// grid (32 n-tiles, 128 row-tiles), one 128x128 tile per CTA, 2 CTAs/SM.
#define G2_SMEM 65536
__global__ void __launch_bounds__(256, 2) k_gemm2_mma() {
    extern __shared__ char smem[];
    uint32_t sb = smem_u32(smem);
    int tid = threadIdx.x, wid = tid >> 5, lane = tid & 31;
    int nbase = blockIdx.x * 128, rowbase = blockIdx.y * 128;
    const uint32_t AHI = 0, ALO = 16384, BHI = 32768, BLO = 49152;

    #pragma unroll
    for (int u = 0; u < 4; u++) {
        int f = tid + u * 256;                     // 0..1023
        int row = f >> 3, cq = f & 7;
        uint32_t off = SW128((uint32_t)(row * 128 + cq * 16));
        *(uint4*)(smem + AHI + off) = *(const uint4*)&g_Hhi[(size_t)(rowbase + row) * 64 + cq * 8];
        *(uint4*)(smem + ALO + off) = *(const uint4*)&g_Hlo[(size_t)(rowbase + row) * 64 + cq * 8];
    }
    #pragma unroll
    for (int u = 0; u < 4; u++) {
        int f = tid + u * 256;
        int n = f >> 3, cq = f & 7;
        uint32_t off = SW128((uint32_t)(n * 128 + cq * 16));
        *(uint4*)(smem + BHI + off) = *(const uint4*)&g_Ehi[(size_t)(nbase + n) * 64 + cq * 8];
        *(uint4*)(smem + BLO + off) = *(const uint4*)&g_Elo[(size_t)(nbase + n) * 64 + cq * 8];
    }
    __syncthreads();

    int warp_m = wid & 3, warp_n = wid >> 2;
    int mbase = warp_m * 32, nb0 = warp_n * 64;
    float acc[2][8][4] = {};
    int a_row = lane & 15;
    int a_kadd = (lane >> 4) << 3;
    int b_row = ((lane >> 4) << 3) + (lane & 7);
    int b_kadd = lane & 8;

    #pragma unroll
    for (int ks = 0; ks < 4; ks++) {
        int k0 = ks * 16;
        uint32_t ahi[2][4], alo[2][4];
        #pragma unroll
        for (int mt = 0; mt < 2; mt++) {
            uint32_t aoff = SW128((uint32_t)((mbase + mt * 16 + a_row) * 128 + (k0 + a_kadd) * 2));
            ldsm4(sb + AHI + aoff, ahi[mt][0], ahi[mt][1], ahi[mt][2], ahi[mt][3]);
            ldsm4(sb + ALO + aoff, alo[mt][0], alo[mt][1], alo[mt][2], alo[mt][3]);
        }
        #pragma unroll
        for (int g = 0; g < 2; g++) {              // n-block pairs {0,1},{2,3}
            uint32_t bh[2][4], bl[2][4];
            #pragma unroll
            for (int j = 0; j < 2; j++) {
                int np = g * 2 + j;
                uint32_t boff = SW128((uint32_t)((nb0 + np * 16 + b_row) * 128 + (k0 + b_kadd) * 2));
                ldsm4(sb + BHI + boff, bh[j][0], bh[j][1], bh[j][2], bh[j][3]);
                ldsm4(sb + BLO + boff, bl[j][0], bl[j][1], bl[j][2], bl[j][3]);
            }
            // pass-ordered: same-acc MMAs are 8 apart
            #pragma unroll
            for (int mt = 0; mt < 2; mt++)
                #pragma unroll
                for (int j = 0; j < 2; j++) {
                    int np = g * 2 + j;
                    mma_bf16(acc[mt][np * 2],     ahi[mt], bh[j]);
                    mma_bf16(acc[mt][np * 2 + 1], ahi[mt], bh[j] + 2);
                }
            #pragma unroll
            for (int mt = 0; mt < 2; mt++)
                #pragma unroll
                for (int j = 0; j < 2; j++) {
                    int np = g * 2 + j;
                    mma_bf16(acc[mt][np * 2],     ahi[mt], bl[j]);
                    mma_bf16(acc[mt][np * 2 + 1], ahi[mt], bl[j] + 2);
                }
            #pragma unroll
            for (int mt = 0; mt < 2; mt++)
                #pragma unroll
                for (int j = 0; j < 2; j++) {
                    int np = g * 2 + j;
                    mma_bf16(acc[mt][np * 2],     alo[mt], bh[j]);
                    mma_bf16(acc[mt][np * 2 + 1], alo[mt], bh[j] + 2);
                }
        }
    }

    // epilogue: fp16 logits
    int cb = (lane & 3) * 2;
    #pragma unroll
    for (int mt = 0; mt < 2; mt++) {
        int r0 = rowbase + mbase + mt * 16 + (lane >> 2);
        #pragma unroll
        for (int half = 0; half < 2; half++) {
            __half* lp = g_logitsH + (size_t)(r0 + half * 8) * NTOT + nbase + nb0;
            #pragma unroll
            for (int nt = 0; nt < 8; nt++) {
                int col = nt * 8 + cb;
                __half2 h = __floats2half2_rn(acc[mt][nt][half * 2], acc[mt][nt][half * 2 + 1]);
                *(__half2*)(lp + col) = h;
            }
        }
    }
}

// ------- softmax + importance-weighted accumulate (fp16 logits) ------------
__global__ void k_softmax(const float* __restrict__ imp) {
    int tid = threadIdx.x;
    int lane = tid & 31, wid = tid >> 5;
    int rb = blockIdx.x * 32;
    __shared__ float wred[8];
    float acc[16] = {};
    int grp = (tid < 128) ? 0 : (tid < 192 ? 1 : 2);

    for (int ri = 0; ri < 32; ri++) {
        int r = rb + ri;
        const uint4* lp = (const uint4*)(g_logitsH + (size_t)r * NTOT + tid * 16);
        uint4 v0 = lp[0];
        uint4 v1 = lp[1];
        float lg[16];
        {
            const uint32_t w[8] = {v0.x, v0.y, v0.z, v0.w, v1.x, v1.y, v1.z, v1.w};
            #pragma unroll
            for (int q = 0; q < 8; q++) {
                __half2 h = *reinterpret_cast<const __half2*>(&w[q]);
                float2 f = __half22float2(h);
                lg[q * 2] = f.x; lg[q * 2 + 1] = f.y;
            }
        }
        float m = -1e30f;
        #pragma unroll
        for (int j = 0; j < 16; j++) m = fmaxf(m, lg[j]);
        #pragma unroll
        for (int o = 16; o; o >>= 1) m = fmaxf(m, __shfl_xor_sync(0xffffffffu, m, o));
        if (lane == 0) wred[wid] = m;
        __syncthreads();
        float gm;
        if (grp == 0) gm = fmaxf(fmaxf(wred[0], wred[1]), fmaxf(wred[2], wred[3]));
        else if (grp == 1) gm = fmaxf(wred[4], wred[5]);
        else gm = fmaxf(wred[6], wred[7]);
        __syncthreads();
        float e[16]; float se = 0.0f;
        #pragma unroll
        for (int j = 0; j < 16; j++) { e[j] = fexp(lg[j] - gm); se += e[j]; }
        #pragma unroll
        for (int o = 16; o; o >>= 1) se += __shfl_xor_sync(0xffffffffu, se, o);
        if (lane == 0) wred[wid] = se;
        __syncthreads();
        float gs;
        if (grp == 0) gs = (wred[0] + wred[1]) + (wred[2] + wred[3]);
        else if (grp == 1) gs = wred[4] + wred[5];
        else gs = wred[6] + wred[7];
        __syncthreads();
        float sc = imp[r] / gs;
        #pragma unroll
        for (int j = 0; j < 16; j++) acc[j] = fmaf(e[j], sc, acc[j]);
    }
    float* pp = g_part + (size_t)blockIdx.x * NTOT + tid * 16;
    #pragma unroll
    for (int q = 0; q < 4; q++)
        *(float4*)&pp[q * 4] = make_float4(acc[q * 4], acc[q * 4 + 1],
                                           acc[q * 4 + 2], acc[q * 4 + 3]);
}

__global__ void k_reduce_part() {
    int t = blockIdx.x * 256 + threadIdx.x;
    int b = t >> 12; int n = t & 4095;
    float s = 0.0f;
    #pragma unroll 8
    for (int p = 0; p < 128; p++) s += g_part[(size_t)(b * 128 + p) * NTOT + n];
    g_d[t] = s;
}

// ---------------- top-k sparsify + output ----------------------------------
__global__ void k_topk(float* __restrict__ out) {
    int b = blockIdx.x / 3, g = blockIdx.x % 3;
    int gsize = (g == 0) ? 2048 : 1024;
    int doff = (g == 0) ? 0 : (g == 1 ? 2048 : 3072);
    int K = (g == 0) ? 8 : (g == 1 ? 4 : 6);
    __shared__ float vals[2048];
    __shared__ float rv[256];
    __shared__ int ri[256];
    __shared__ float selv[8];
    __shared__ int seli[8];
    __shared__ float ssum;
    int tid = threadIdx.x;
    for (int i = tid; i < gsize; i += 256) vals[i] = g_d[b * 4096 + doff + i];
    float* ob = out + b * 5120;
    if (g == 0)      { for (int i = tid; i < 2048; i += 256) ob[i] = 0.0f; }
    else if (g == 1) { for (int i = tid; i < 2048; i += 256) ob[2048 + i] = 0.0f; }
    else             { for (int i = tid; i < 1024; i += 256) ob[4096 + i] = 0.0f; }
    __syncthreads();

    for (int kk = 0; kk < K; kk++) {
        float bv = -1e30f; int bi = 0x7fffffff;
        for (int i = tid; i < gsize; i += 256) {
            float v = vals[i];
            if (v > bv || (v == bv && i < bi)) { bv = v; bi = i; }
        }
        rv[tid] = bv; ri[tid] = bi;
        __syncthreads();
        for (int s = 128; s; s >>= 1) {
            if (tid < s) {
                float v2 = rv[tid + s]; int i2 = ri[tid + s];
                if (v2 > rv[tid] || (v2 == rv[tid] && i2 < ri[tid])) { rv[tid] = v2; ri[tid] = i2; }
            }
            __syncthreads();
        }
        if (tid == 0) { selv[kk] = rv[0]; seli[kk] = ri[0]; vals[ri[0]] = -1e30f; }
        __syncthreads();
    }
    if (tid == 0) {
        float s = 0.0f;
        for (int kk = 0; kk < K; kk++) s += selv[kk];
        ssum = 1.0f / (s + 1e-8f);
    }
    __syncthreads();
    if (tid < K) {
        float wv = selv[tid] * ssum;
        int idx = seli[tid];
        if (g == 0) ob[idx] = wv;
        else if (g == 1) { ob[2048 + idx] = wv; ob[3072 + idx] = wv; }
        else ob[4096 + idx] = wv;
    }
}

// ---------------------------------------------------------------------------
extern "C" void kernel_launch(void* const* d_in, const int* in_sizes, int n_in,
                              void* d_out, int out_size) {
    const float *x = nullptr, *imp = nullptr, *W = nullptr, *bias = nullptr, *emb = nullptr;
    for (int i = 0; i < n_in; i++) {
        switch (in_sizes[i]) {
            case 33554432: x    = (const float*)d_in[i]; break;  // 4*4096*2048
            case 16384:    imp  = (const float*)d_in[i]; break;  // 4*4096
            case 131072:   W    = (const float*)d_in[i]; break;  // 2048*64
            case 64:       bias = (const float*)d_in[i]; break;  // 64
            case 262144:   emb  = (const float*)d_in[i]; break;  // 4096*64
            default: break;
        }
    }
    cudaFuncSetAttribute(k_gemm1_mma, cudaFuncAttributeMaxDynamicSharedMemorySize, G1_SMEM);
    cudaFuncSetAttribute(k_gemm2_mma, cudaFuncAttributeMaxDynamicSharedMemorySize, G2_SMEM);

    k_norm_emb<<<512, 256>>>(emb);
    k_prep_w<<<512, 256>>>(W);
    k_gemm1_mma<<<dim3(256, 2), 256, G1_SMEM>>>(x);
    k_combine<<<2048, 256>>>(bias);
    k_gemm2_mma<<<dim3(32, 128), 256, G2_SMEM>>>();
    k_softmax<<<512, 256>>>(imp);
    k_reduce_part<<<64, 256>>>();
    k_topk<<<12, 256>>>((float*)d_out);
}

// round 6
// speedup vs baseline: 2.0282x; 1.0071x over previous
#include <cuda_runtime.h>
#include <cuda_fp16.h>
#include <cuda_bf16.h>
#include <cstdint>

#define ROWS_TOTAL 16384
#define DIM 2048
#define NTOT 4096

// ---------------- device scratch (static; no runtime alloc) ----------------
__device__ __align__(16) __nv_bfloat16 g_Ehi[NTOT * 64];
__device__ __align__(16) __nv_bfloat16 g_Elo[NTOT * 64];
__device__ __align__(16) __nv_bfloat16 g_Whi[64 * DIM];
__device__ __align__(16) __nv_bfloat16 g_Wlo[64 * DIM];
__device__ __align__(16) float g_h1p[2 * (size_t)ROWS_TOTAL * 64];   // K-split partials, 8MB
__device__ __align__(16) __nv_bfloat16 g_Hhi[(size_t)ROWS_TOTAL * 64];
__device__ __align__(16) __nv_bfloat16 g_Hlo[(size_t)ROWS_TOTAL * 64];
__device__ __align__(16) __half g_E[(size_t)ROWS_TOTAL * NTOT];      // exp(logit-8), 134MB
__device__ __align__(16) float g_rsum[(size_t)ROWS_TOTAL * 64];      // per-tile row sums, 4MB
__device__ __align__(16) float g_scale[3 * ROWS_TOTAL];              // imp/groupsum
__device__ __align__(16) float g_part[512 * NTOT];
__device__ float g_d[4 * NTOT];

// ---------------- helpers ----------------
__device__ __forceinline__ uint32_t smem_u32(const void* p) {
    uint32_t a;
    asm("{ .reg .u64 t; cvta.to.shared.u64 t, %1; cvt.u32.u64 %0, t; }" : "=r"(a) : "l"(p));
    return a;
}
#define SW128(o) ((o) ^ (((o) >> 3) & 0x70))

__device__ __forceinline__ void ldsm4(uint32_t addr, uint32_t& r0, uint32_t& r1,
                                      uint32_t& r2, uint32_t& r3) {
    asm volatile("ldmatrix.sync.aligned.m8n8.x4.shared.b16 {%0,%1,%2,%3}, [%4];"
                 : "=r"(r0), "=r"(r1), "=r"(r2), "=r"(r3) : "r"(addr));
}
__device__ __forceinline__ void mma_bf16(float* c, const uint32_t* a, const uint32_t* b) {
    asm volatile(
        "mma.sync.aligned.m16n8k16.row.col.f32.bf16.bf16.f32 "
        "{%0,%1,%2,%3}, {%4,%5,%6,%7}, {%8,%9}, {%0,%1,%2,%3};"
        : "+f"(c[0]), "+f"(c[1]), "+f"(c[2]), "+f"(c[3])
        : "r"(a[0]), "r"(a[1]), "r"(a[2]), "r"(a[3]), "r"(b[0]), "r"(b[1]));
}

__device__ __forceinline__ uint32_t split_pack_hi(float a, float b, uint32_t& lo) {
    __nv_bfloat162 h = __floats2bfloat162_rn(a, b);
    float ra = a - __bfloat162float(h.x);
    float rb = b - __bfloat162float(h.y);
    __nv_bfloat162 l = __floats2bfloat162_rn(ra, rb);
    lo = *reinterpret_cast<uint32_t*>(&l);
    return *reinterpret_cast<uint32_t*>(&h);
}

// fast exp (FFMA-only, avoids MUFU bottleneck)
__device__ __forceinline__ float fexp(float x) {
    x = fmaxf(x, -87.0f);
    float y = x * 1.4426950408889634f;
    float n = rintf(y);
    float t = (y - n) * 0.6931471805599453f;
    float p = fmaf(t, 8.3333333e-3f, 4.1666667e-2f);
    p = fmaf(p, t, 0.16666667f);
    p = fmaf(p, t, 0.5f);
    p = fmaf(p, t, 1.0f);
    p = fmaf(p, t, 1.0f);
    int e = (int)n;
    float s = __int_as_float((e + 127) << 23);
    return p * s;
}

// ---------------- prep kernels ----------------
__global__ void k_norm_emb(const float* __restrict__ emb) {
    int n = blockIdx.x * 8 + (threadIdx.x >> 5);
    int lane = threadIdx.x & 31;
    float v0 = emb[n * 64 + lane];
    float v1 = emb[n * 64 + lane + 32];
    float ss = v0 * v0 + v1 * v1;
    #pragma unroll
    for (int o = 16; o; o >>= 1) ss += __shfl_xor_sync(0xffffffffu, ss, o);
    float inv = rsqrtf(ss);
    float e0 = v0 * inv, e1 = v1 * inv;
    __nv_bfloat16 h0 = __float2bfloat16_rn(e0);
    __nv_bfloat16 h1 = __float2bfloat16_rn(e1);
    g_Ehi[n * 64 + lane] = h0;
    g_Ehi[n * 64 + lane + 32] = h1;
    g_Elo[n * 64 + lane] = __float2bfloat16_rn(e0 - __bfloat162float(h0));
    g_Elo[n * 64 + lane + 32] = __float2bfloat16_rn(e1 - __bfloat162float(h1));
}

__global__ void k_prep_w(const float* __restrict__ W) {
    int t = blockIdx.x * 256 + threadIdx.x;   // t = k*64 + n
    if (t >= DIM * 64) return;
    int k = t >> 6, n = t & 63;
    float v = W[t];
    __nv_bfloat16 h = __float2bfloat16_rn(v);
    g_Whi[n * DIM + k] = h;
    g_Wlo[n * DIM + k] = __float2bfloat16_rn(v - __bfloat162float(h));
}

// ---------------- GEMM1: h-partials = x @ W (mma.sync, split bf16) ---------
#define G1_SMEM 65536
__global__ void __launch_bounds__(256, 2) k_gemm1_mma(const float* __restrict__ X) {
    extern __shared__ char smem[];
    uint32_t sb = smem_u32(smem);
    int tid = threadIdx.x, wid = tid >> 5, lane = tid & 31;
    int rowbase = blockIdx.x * 64;
    int kbase = blockIdx.y * 1024;
    const uint32_t XHI = 0, XLO = 8192, WHI = 16384, WLO = 24576, BUF = 32768;

    float acc[4][4] = {};
    float4 xv[4];
    uint4 wv[4];

    int warp_m = wid & 3, warp_n = wid >> 2;
    int mbase = warp_m * 16, nb0 = warp_n * 32;
    int a_row = lane & 15;
    int a_kadd = (lane >> 4) << 3;
    int b_row = ((lane >> 4) << 3) + (lane & 7);
    int b_kadd = lane & 8;

    auto ldg_chunk = [&](int c) {
        int kb = kbase + c * 64;
        #pragma unroll
        for (int u = 0; u < 4; u++) {
            int f = tid + u * 256;
            int row = f >> 4, kq = f & 15;
            xv[u] = *(const float4*)&X[(size_t)(rowbase + row) * DIM + kb + kq * 4];
        }
        #pragma unroll
        for (int u = 0; u < 2; u++) {
            int f = tid + u * 256;
            int n = f >> 3, cq = f & 7;
            wv[u * 2]     = *(const uint4*)&g_Whi[n * DIM + kb + cq * 8];
            wv[u * 2 + 1] = *(const uint4*)&g_Wlo[n * DIM + kb + cq * 8];
        }
    };
    auto sts_chunk = [&](int c) {
        int b = c & 1;
        #pragma unroll
        for (int u = 0; u < 4; u++) {
            int f = tid + u * 256;
            int row = f >> 4, kq = f & 15;
            uint32_t l0, l1;
            uint32_t h0 = split_pack_hi(xv[u].x, xv[u].y, l0);
            uint32_t h1 = split_pack_hi(xv[u].z, xv[u].w, l1);
            uint32_t off = SW128((uint32_t)(row * 128 + kq * 8));
            *(uint2*)(smem + XHI + b * BUF + off) = make_uint2(h0, h1);
            *(uint2*)(smem + XLO + b * BUF + off) = make_uint2(l0, l1);
        }
        #pragma unroll
        for (int u = 0; u < 2; u++) {
            int f = tid + u * 256;
            int n = f >> 3, cq = f & 7;
            uint32_t off = SW128((uint32_t)(n * 128 + cq * 16));
            *(uint4*)(smem + WHI + b * BUF + off) = wv[u * 2];
            *(uint4*)(smem + WLO + b * BUF + off) = wv[u * 2 + 1];
        }
    };

    ldg_chunk(0);
    sts_chunk(0);
    __syncthreads();
    for (int c = 0; c < 16; c++) {
        if (c + 1 < 16) ldg_chunk(c + 1);
        int b = c & 1;
        uint32_t xh = sb + XHI + b * BUF, xl = sb + XLO + b * BUF;
        uint32_t wh = sb + WHI + b * BUF, wl = sb + WLO + b * BUF;
        #pragma unroll
        for (int ks = 0; ks < 4; ks++) {
            int k0 = ks * 16;
            uint32_t ahi[4], alo[4];
            uint32_t aoff = SW128((uint32_t)((mbase + a_row) * 128 + (k0 + a_kadd) * 2));
            ldsm4(xh + aoff, ahi[0], ahi[1], ahi[2], ahi[3]);
            ldsm4(xl + aoff, alo[0], alo[1], alo[2], alo[3]);
            uint32_t bh[2][4], bl[2][4];
            #pragma unroll
            for (int nh = 0; nh < 2; nh++) {
                uint32_t boff = SW128((uint32_t)((nb0 + nh * 16 + b_row) * 128 + (k0 + b_kadd) * 2));
                ldsm4(wh + boff, bh[nh][0], bh[nh][1], bh[nh][2], bh[nh][3]);
                ldsm4(wl + boff, bl[nh][0], bl[nh][1], bl[nh][2], bl[nh][3]);
            }
            #pragma unroll
            for (int nh = 0; nh < 2; nh++) {
                mma_bf16(acc[nh * 2],     ahi, bh[nh]);
                mma_bf16(acc[nh * 2 + 1], ahi, bh[nh] + 2);
            }
            #pragma unroll
            for (int nh = 0; nh < 2; nh++) {
                mma_bf16(acc[nh * 2],     ahi, bl[nh]);
                mma_bf16(acc[nh * 2 + 1], ahi, bl[nh] + 2);
            }
            #pragma unroll
            for (int nh = 0; nh < 2; nh++) {
                mma_bf16(acc[nh * 2],     alo, bh[nh]);
                mma_bf16(acc[nh * 2 + 1], alo, bh[nh] + 2);
            }
        }
        if (c + 1 < 16) sts_chunk(c + 1);
        __syncthreads();
    }

    float* pbase = g_h1p + (size_t)blockIdx.y * ROWS_TOTAL * 64;
    int r0 = rowbase + mbase + (lane >> 2);
    int cb = (lane & 3) * 2;
    #pragma unroll
    for (int half = 0; half < 2; half++) {
        int row = r0 + half * 8;
        #pragma unroll
        for (int nt = 0; nt < 4; nt++) {
            int col = nb0 + nt * 8 + cb;
            *(float2*)&pbase[(size_t)row * 64 + col] =
                make_float2(acc[nt][half * 2], acc[nt][half * 2 + 1]);
        }
    }
}

// ---------------- combine partials + bias -> split bf16 h ------------------
__global__ void k_combine(const float* __restrict__ bias) {
    int t = blockIdx.x * 256 + threadIdx.x;
    int idx = t * 2;
    int col = idx & 63;
    float2 p0 = *(const float2*)&g_h1p[idx];
    float2 p1 = *(const float2*)&g_h1p[idx + (size_t)ROWS_TOTAL * 64];
    float f0 = p0.x + p1.x + bias[col];
    float f1 = p0.y + p1.y + bias[col + 1];
    uint32_t lo;
    uint32_t hi = split_pack_hi(f0, f1, lo);
    *(uint32_t*)&g_Hhi[idx] = hi;
    *(uint32_t*)&g_Hlo[idx] = lo;
}

// ------ GEMM2 fused: E = exp(H @ embn^T - 8), per-tile row sums ------------
// grid (64 n-tiles of 64, 128 row-tiles of 128). Warp tile 32x32 (8 warps 4x2).
#define G2_SMEM 50176
__global__ void __launch_bounds__(256, 2) k_gemm2_mma() {
    extern __shared__ char smem[];
    uint32_t sb = smem_u32(smem);
    int tid = threadIdx.x, wid = tid >> 5, lane = tid & 31;
    int nbase = blockIdx.x * 64, rowbase = blockIdx.y * 128;
    const uint32_t AHI = 0, ALO = 16384, BHI = 32768, BLO = 40960, RS = 49152;

    #pragma unroll
    for (int u = 0; u < 4; u++) {
        int f = tid + u * 256;                     // 0..1023
        int row = f >> 3, cq = f & 7;
        uint32_t off = SW128((uint32_t)(row * 128 + cq * 16));
        *(uint4*)(smem + AHI + off) = *(const uint4*)&g_Hhi[(size_t)(rowbase + row) * 64 + cq * 8];
        *(uint4*)(smem + ALO + off) = *(const uint4*)&g_Hlo[(size_t)(rowbase + row) * 64 + cq * 8];
    }
    #pragma unroll
    for (int u = 0; u < 2; u++) {
        int f = tid + u * 256;                     // 0..511
        int n = f >> 3, cq = f & 7;
        uint32_t off = SW128((uint32_t)(n * 128 + cq * 16));
        *(uint4*)(smem + BHI + off) = *(const uint4*)&g_Ehi[(size_t)(nbase + n) * 64 + cq * 8];
        *(uint4*)(smem + BLO + off) = *(const uint4*)&g_Elo[(size_t)(nbase + n) * 64 + cq * 8];
    }
    __syncthreads();

    int warp_m = wid & 3, warp_n = wid >> 2;       // 4 x 2
    int mbase = warp_m * 32, nb0 = warp_n * 32;
    float acc[2][4][4] = {};                       // [mt][n8 block][frag]
    int a_row = lane & 15;
    int a_kadd = (lane >> 4) << 3;
    int b_row = ((lane >> 4) << 3) + (lane & 7);
    int b_kadd = lane & 8;

    #pragma unroll
    for (int ks = 0; ks < 4; ks++) {
        int k0 = ks * 16;
        uint32_t ahi[2][4], alo[2][4];
        #pragma unroll
        for (int mt = 0; mt < 2; mt++) {
            uint32_t aoff = SW128((uint32_t)((mbase + mt * 16 + a_row) * 128 + (k0 + a_kadd) * 2));
            ldsm4(sb + AHI + aoff, ahi[mt][0], ahi[mt][1], ahi[mt][2], ahi[mt][3]);
            ldsm4(sb + ALO + aoff, alo[mt][0], alo[mt][1], alo[mt][2], alo[mt][3]);
        }
        uint32_t bh[2][4], bl[2][4];
        #pragma unroll
        for (int np = 0; np < 2; np++) {
            uint32_t boff = SW128((uint32_t)((nb0 + np * 16 + b_row) * 128 + (k0 + b_kadd) * 2));
            ldsm4(sb + BHI + boff, bh[np][0], bh[np][1], bh[np][2], bh[np][3]);
            ldsm4(sb + BLO + boff, bl[np][0], bl[np][1], bl[np][2], bl[np][3]);
        }
        // pass-ordered: same-acc MMAs are 8 apart
        #pragma unroll
        for (int mt = 0; mt < 2; mt++)
            #pragma unroll
            for (int np = 0; np < 2; np++) {
                mma_bf16(acc[mt][np * 2],     ahi[mt], bh[np]);
                mma_bf16(acc[mt][np * 2 + 1], ahi[mt], bh[np] + 2);
            }
        #pragma unroll
        for (int mt = 0; mt < 2; mt++)
            #pragma unroll
            for (int np = 0; np < 2; np++) {
                mma_bf16(acc[mt][np * 2],     ahi[mt], bl[np]);
                mma_bf16(acc[mt][np * 2 + 1], ahi[mt], bl[np] + 2);
            }
        #pragma unroll
        for (int mt = 0; mt < 2; mt++)
            #pragma unroll
            for (int np = 0; np < 2; np++) {
                mma_bf16(acc[mt][np * 2],     alo[mt], bh[np]);
                mma_bf16(acc[mt][np * 2 + 1], alo[mt], bh[np] + 2);
            }
    }

    // fused epilogue: E = exp(logit - 8) (fp16), per-tile fp32 row sums
    float* rs = (float*)(smem + RS);               // [128][2]
    int cb = (lane & 3) * 2;
    #pragma unroll
    for (int mt = 0; mt < 2; mt++) {
        #pragma unroll
        for (int half = 0; half < 2; half++) {
            int rloc = mbase + mt * 16 + half * 8 + (lane >> 2);
            __half* erow = g_E + (size_t)(rowbase + rloc) * NTOT + nbase + nb0;
            float rsum = 0.0f;
            #pragma unroll
            for (int j = 0; j < 4; j++) {
                float e0 = fexp(acc[mt][j][half * 2]     - 8.0f);
                float e1 = fexp(acc[mt][j][half * 2 + 1] - 8.0f);
                rsum += e0 + e1;
                *(__half2*)(erow + j * 8 + cb) = __floats2half2_rn(e0, e1);
            }
            rsum += __shfl_xor_sync(0xffffffffu, rsum, 1);
            rsum += __shfl_xor_sync(0xffffffffu, rsum, 2);
            if ((lane & 3) == 0) rs[rloc * 2 + warp_n] = rsum;
        }
    }
    __syncthreads();
    if (tid < 128)
        g_rsum[(size_t)(rowbase + tid) * 64 + blockIdx.x] = rs[tid * 2] + rs[tid * 2 + 1];
}

// ---------------- group scales: imp / sum(exp) ------------------------------
__global__ void k_rsum_scale(const float* __restrict__ imp) {
    int r = blockIdx.x * 256 + threadIdx.x;        // 0..16383
    const float4* p = (const float4*)(g_rsum + (size_t)r * 64);
    float sC = 0, sQ = 0, sV = 0;
    #pragma unroll
    for (int i = 0; i < 8; i++)  { float4 v = p[i];  sC += (v.x + v.y) + (v.z + v.w); }
    #pragma unroll
    for (int i = 8; i < 12; i++) { float4 v = p[i];  sQ += (v.x + v.y) + (v.z + v.w); }
    #pragma unroll
    for (int i = 12; i < 16; i++){ float4 v = p[i];  sV += (v.x + v.y) + (v.z + v.w); }
    float im = imp[r];
    g_scale[r]                  = im / sC;
    g_scale[ROWS_TOTAL + r]     = im / sQ;
    g_scale[2 * ROWS_TOTAL + r] = im / sV;
}

// ---------------- accumulate d partials (pure streaming) --------------------
__global__ void k_accum() {
    int tid = threadIdx.x;
    int rb = blockIdx.x * 32;
    int grp = (tid < 128) ? 0 : (tid < 192 ? 1 : 2);
    float acc[16] = {};
    for (int ri = 0; ri < 32; ri++) {
        int r = rb + ri;
        float sc = g_scale[grp * ROWS_TOTAL + r];
        const uint4* lp = (const uint4*)(g_E + (size_t)r * NTOT + tid * 16);
        uint4 v0 = lp[0];
        uint4 v1 = lp[1];
        const uint32_t w[8] = {v0.x, v0.y, v0.z, v0.w, v1.x, v1.y, v1.z, v1.w};
        #pragma unroll
        for (int q = 0; q < 8; q++) {
            float2 f = __half22float2(*reinterpret_cast<const __half2*>(&w[q]));
            acc[q * 2]     = fmaf(f.x, sc, acc[q * 2]);
            acc[q * 2 + 1] = fmaf(f.y, sc, acc[q * 2 + 1]);
        }
    }
    float* pp = g_part + (size_t)blockIdx.x * NTOT + tid * 16;
    #pragma unroll
    for (int q = 0; q < 4; q++)
        *(float4*)&pp[q * 4] = make_float4(acc[q * 4], acc[q * 4 + 1],
                                           acc[q * 4 + 2], acc[q * 4 + 3]);
}

__global__ void k_reduce_part() {
    int t = blockIdx.x * 256 + threadIdx.x;
    int b = t >> 12; int n = t & 4095;
    float s = 0.0f;
    #pragma unroll 8
    for (int p = 0; p < 128; p++) s += g_part[(size_t)(b * 128 + p) * NTOT + n];
    g_d[t] = s;
}

// ---------------- top-k sparsify + output ----------------------------------
__global__ void k_topk(float* __restrict__ out) {
    int b = blockIdx.x / 3, g = blockIdx.x % 3;
    int gsize = (g == 0) ? 2048 : 1024;
    int doff = (g == 0) ? 0 : (g == 1 ? 2048 : 3072);
    int K = (g == 0) ? 8 : (g == 1 ? 4 : 6);
    __shared__ float vals[2048];
    __shared__ float rv[256];
    __shared__ int ri[256];
    __shared__ float selv[8];
    __shared__ int seli[8];
    __shared__ float ssum;
    int tid = threadIdx.x;
    for (int i = tid; i < gsize; i += 256) vals[i] = g_d[b * 4096 + doff + i];
    float* ob = out + b * 5120;
    if (g == 0)      { for (int i = tid; i < 2048; i += 256) ob[i] = 0.0f; }
    else if (g == 1) { for (int i = tid; i < 2048; i += 256) ob[2048 + i] = 0.0f; }
    else             { for (int i = tid; i < 1024; i += 256) ob[4096 + i] = 0.0f; }
    __syncthreads();

    for (int kk = 0; kk < K; kk++) {
        float bv = -1e30f; int bi = 0x7fffffff;
        for (int i = tid; i < gsize; i += 256) {
            float v = vals[i];
            if (v > bv || (v == bv && i < bi)) { bv = v; bi = i; }
        }
        rv[tid] = bv; ri[tid] = bi;
        __syncthreads();
        for (int s = 128; s; s >>= 1) {
            if (tid < s) {
                float v2 = rv[tid + s]; int i2 = ri[tid + s];
                if (v2 > rv[tid] || (v2 == rv[tid] && i2 < ri[tid])) { rv[tid] = v2; ri[tid] = i2; }
            }
            __syncthreads();
        }
        if (tid == 0) { selv[kk] = rv[0]; seli[kk] = ri[0]; vals[ri[0]] = -1e30f; }
        __syncthreads();
    }
    if (tid == 0) {
        float s = 0.0f;
        for (int kk = 0; kk < K; kk++) s += selv[kk];
        ssum = 1.0f / (s + 1e-8f);
    }
    __syncthreads();
    if (tid < K) {
        float wv = selv[tid] * ssum;
        int idx = seli[tid];
        if (g == 0) ob[idx] = wv;
        else if (g == 1) { ob[2048 + idx] = wv; ob[3072 + idx] = wv; }
        else ob[4096 + idx] = wv;
    }
}

// ---------------------------------------------------------------------------
extern "C" void kernel_launch(void* const* d_in, const int* in_sizes, int n_in,
                              void* d_out, int out_size) {
    const float *x = nullptr, *imp = nullptr, *W = nullptr, *bias = nullptr, *emb = nullptr;
    for (int i = 0; i < n_in; i++) {
        switch (in_sizes[i]) {
            case 33554432: x    = (const float*)d_in[i]; break;  // 4*4096*2048
            case 16384:    imp  = (const float*)d_in[i]; break;  // 4*4096
            case 131072:   W    = (const float*)d_in[i]; break;  // 2048*64
            case 64:       bias = (const float*)d_in[i]; break;  // 64
            case 262144:   emb  = (const float*)d_in[i]; break;  // 4096*64
            default: break;
        }
    }
    cudaFuncSetAttribute(k_gemm1_mma, cudaFuncAttributeMaxDynamicSharedMemorySize, G1_SMEM);
    cudaFuncSetAttribute(k_gemm2_mma, cudaFuncAttributeMaxDynamicSharedMemorySize, G2_SMEM);

    k_norm_emb<<<512, 256>>>(emb);
    k_prep_w<<<512, 256>>>(W);
    k_gemm1_mma<<<dim3(256, 2), 256, G1_SMEM>>>(x);
    k_combine<<<2048, 256>>>(bias);
    k_gemm2_mma<<<dim3(64, 128), 256, G2_SMEM>>>();
    k_rsum_scale<<<64, 256>>>(imp);
    k_accum<<<512, 256>>>();
    k_reduce_part<<<64, 256>>>();
    k_topk<<<12, 256>>>((float*)d_out);
}

// round 8
// speedup vs baseline: 2.0978x; 1.0343x over previous
#include <cuda_runtime.h>
#include <cuda_fp16.h>
#include <cuda_bf16.h>
#include <cstdint>

#define ROWS_TOTAL 16384
#define DIM 2048
#define NTOT 4096

// ---------------- device scratch (static; no runtime alloc) ----------------
__device__ __align__(16) __nv_bfloat16 g_Ehi[NTOT * 64];
__device__ __align__(16) __nv_bfloat16 g_Elo[NTOT * 64];
__device__ __align__(16) __nv_bfloat16 g_Whi[64 * DIM];
__device__ __align__(16) __nv_bfloat16 g_Wlo[64 * DIM];
__device__ __align__(16) float g_h1p[2 * (size_t)ROWS_TOTAL * 64];   // K-split partials, 8MB
__device__ __align__(16) __nv_bfloat16 g_Hhi[(size_t)ROWS_TOTAL * 64];
__device__ __align__(16) __nv_bfloat16 g_Hlo[(size_t)ROWS_TOTAL * 64];
__device__ __align__(16) __half g_E[(size_t)ROWS_TOTAL * NTOT];      // exp(logit-8), 134MB
__device__ __align__(16) float g_rsum[(size_t)ROWS_TOTAL * 64];      // per-tile row sums
__device__ __align__(16) float g_scale[3 * ROWS_TOTAL];              // imp/groupsum
__device__ __align__(16) float g_part[512 * NTOT];
__device__ float g_d[4 * NTOT];

// ---------------- helpers ----------------
__device__ __forceinline__ uint32_t smem_u32(const void* p) {
    uint32_t a;
    asm("{ .reg .u64 t; cvta.to.shared.u64 t, %1; cvt.u32.u64 %0, t; }" : "=r"(a) : "l"(p));
    return a;
}
#define SW128(o) ((o) ^ (((o) >> 3) & 0x70))

__device__ __forceinline__ void ldsm4(uint32_t addr, uint32_t& r0, uint32_t& r1,
                                      uint32_t& r2, uint32_t& r3) {
    asm volatile("ldmatrix.sync.aligned.m8n8.x4.shared.b16 {%0,%1,%2,%3}, [%4];"
                 : "=r"(r0), "=r"(r1), "=r"(r2), "=r"(r3) : "r"(addr));
}
__device__ __forceinline__ void mma_bf16(float* c, const uint32_t* a, const uint32_t* b) {
    asm volatile(
        "mma.sync.aligned.m16n8k16.row.col.f32.bf16.bf16.f32 "
        "{%0,%1,%2,%3}, {%4,%5,%6,%7}, {%8,%9}, {%0,%1,%2,%3};"
        : "+f"(c[0]), "+f"(c[1]), "+f"(c[2]), "+f"(c[3])
        : "r"(a[0]), "r"(a[1]), "r"(a[2]), "r"(a[3]), "r"(b[0]), "r"(b[1]));
}

__device__ __forceinline__ uint32_t split_pack_hi(float a, float b, uint32_t& lo) {
    __nv_bfloat162 h = __floats2bfloat162_rn(a, b);
    float ra = a - __bfloat162float(h.x);
    float rb = b - __bfloat162float(h.y);
    __nv_bfloat162 l = __floats2bfloat162_rn(ra, rb);
    lo = *reinterpret_cast<uint32_t*>(&l);
    return *reinterpret_cast<uint32_t*>(&h);
}

// ---------------- prep kernels ----------------
__global__ void k_norm_emb(const float* __restrict__ emb) {
    int n = blockIdx.x * 8 + (threadIdx.x >> 5);
    int lane = threadIdx.x & 31;
    float v0 = emb[n * 64 + lane];
    float v1 = emb[n * 64 + lane + 32];
    float ss = v0 * v0 + v1 * v1;
    #pragma unroll
    for (int o = 16; o; o >>= 1) ss += __shfl_xor_sync(0xffffffffu, ss, o);
    float inv = rsqrtf(ss);
    float e0 = v0 * inv, e1 = v1 * inv;
    __nv_bfloat16 h0 = __float2bfloat16_rn(e0);
    __nv_bfloat16 h1 = __float2bfloat16_rn(e1);
    g_Ehi[n * 64 + lane] = h0;
    g_Ehi[n * 64 + lane + 32] = h1;
    g_Elo[n * 64 + lane] = __float2bfloat16_rn(e0 - __bfloat162float(h0));
    g_Elo[n * 64 + lane + 32] = __float2bfloat16_rn(e1 - __bfloat162float(h1));
}

__global__ void k_prep_w(const float* __restrict__ W) {
    int t = blockIdx.x * 256 + threadIdx.x;   // t = k*64 + n
    if (t >= DIM * 64) return;
    int k = t >> 6, n = t & 63;
    float v = W[t];
    __nv_bfloat16 h = __float2bfloat16_rn(v);
    g_Whi[n * DIM + k] = h;
    g_Wlo[n * DIM + k] = __float2bfloat16_rn(v - __bfloat162float(h));
}

// profiler-alignment dummy (also deterministic init of g_d)
__global__ void k_zero() {
    int t = blockIdx.x * 256 + threadIdx.x;
    if (t < 4 * NTOT) g_d[t] = 0.0f;
}

// ---------------- GEMM1: h-partials = x @ W (mma.sync, split bf16) ---------
#define G1_SMEM 65536
__global__ void __launch_bounds__(256, 2) k_gemm1_mma(const float* __restrict__ X) {
    extern __shared__ char smem[];
    uint32_t sb = smem_u32(smem);
    int tid = threadIdx.x, wid = tid >> 5, lane = tid & 31;
    int rowbase = blockIdx.x * 64;
    int kbase = blockIdx.y * 1024;
    const uint32_t XHI = 0, XLO = 8192, WHI = 16384, WLO = 24576, BUF = 32768;

    float acc[4][4] = {};
    float4 xv[4];
    uint4 wv[4];

    int warp_m = wid & 3, warp_n = wid >> 2;
    int mbase = warp_m * 16, nb0 = warp_n * 32;
    int a_row = lane & 15;
    int a_kadd = (lane >> 4) << 3;
    int b_row = ((lane >> 4) << 3) + (lane & 7);
    int b_kadd = lane & 8;

    auto ldg_chunk = [&](int c) {
        int kb = kbase + c * 64;
        #pragma unroll
        for (int u = 0; u < 4; u++) {
            int f = tid + u * 256;
            int row = f >> 4, kq = f & 15;
            xv[u] = *(const float4*)&X[(size_t)(rowbase + row) * DIM + kb + kq * 4];
        }
        #pragma unroll
        for (int u = 0; u < 2; u++) {
            int f = tid + u * 256;
            int n = f >> 3, cq = f & 7;
            wv[u * 2]     = *(const uint4*)&g_Whi[n * DIM + kb + cq * 8];
            wv[u * 2 + 1] = *(const uint4*)&g_Wlo[n * DIM + kb + cq * 8];
        }
    };
    auto sts_chunk = [&](int c) {
        int b = c & 1;
        #pragma unroll
        for (int u = 0; u < 4; u++) {
            int f = tid + u * 256;
            int row = f >> 4, kq = f & 15;
            uint32_t l0, l1;
            uint32_t h0 = split_pack_hi(xv[u].x, xv[u].y, l0);
            uint32_t h1 = split_pack_hi(xv[u].z, xv[u].w, l1);
            uint32_t off = SW128((uint32_t)(row * 128 + kq * 8));
            *(uint2*)(smem + XHI + b * BUF + off) = make_uint2(h0, h1);
            *(uint2*)(smem + XLO + b * BUF + off) = make_uint2(l0, l1);
        }
        #pragma unroll
        for (int u = 0; u < 2; u++) {
            int f = tid + u * 256;
            int n = f >> 3, cq = f & 7;
            uint32_t off = SW128((uint32_t)(n * 128 + cq * 16));
            *(uint4*)(smem + WHI + b * BUF + off) = wv[u * 2];
            *(uint4*)(smem + WLO + b * BUF + off) = wv[u * 2 + 1];
        }
    };

    ldg_chunk(0);
    sts_chunk(0);
    __syncthreads();
    for (int c = 0; c < 16; c++) {
        if (c + 1 < 16) ldg_chunk(c + 1);
        int b = c & 1;
        uint32_t xh = sb + XHI + b * BUF, xl = sb + XLO + b * BUF;
        uint32_t wh = sb + WHI + b * BUF, wl = sb + WLO + b * BUF;
        #pragma unroll
        for (int ks = 0; ks < 4; ks++) {
            int k0 = ks * 16;
            uint32_t ahi[4], alo[4];
            uint32_t aoff = SW128((uint32_t)((mbase + a_row) * 128 + (k0 + a_kadd) * 2));
            ldsm4(xh + aoff, ahi[0], ahi[1], ahi[2], ahi[3]);
            ldsm4(xl + aoff, alo[0], alo[1], alo[2], alo[3]);
            uint32_t bh[2][4], bl[2][4];
            #pragma unroll
            for (int nh = 0; nh < 2; nh++) {
                uint32_t boff = SW128((uint32_t)((nb0 + nh * 16 + b_row) * 128 + (k0 + b_kadd) * 2));
                ldsm4(wh + boff, bh[nh][0], bh[nh][1], bh[nh][2], bh[nh][3]);
                ldsm4(wl + boff, bl[nh][0], bl[nh][1], bl[nh][2], bl[nh][3]);
            }
            #pragma unroll
            for (int nh = 0; nh < 2; nh++) {
                mma_bf16(acc[nh * 2],     ahi, bh[nh]);
                mma_bf16(acc[nh * 2 + 1], ahi, bh[nh] + 2);
            }
            #pragma unroll
            for (int nh = 0; nh < 2; nh++) {
                mma_bf16(acc[nh * 2],     ahi, bl[nh]);
                mma_bf16(acc[nh * 2 + 1], ahi, bl[nh] + 2);
            }
            #pragma unroll
            for (int nh = 0; nh < 2; nh++) {
                mma_bf16(acc[nh * 2],     alo, bh[nh]);
                mma_bf16(acc[nh * 2 + 1], alo, bh[nh] + 2);
            }
        }
        if (c + 1 < 16) sts_chunk(c + 1);
        __syncthreads();
    }

    float* pbase = g_h1p + (size_t)blockIdx.y * ROWS_TOTAL * 64;
    int r0 = rowbase + mbase + (lane >> 2);
    int cb = (lane & 3) * 2;
    #pragma unroll
    for (int half = 0; half < 2; half++) {
        int row = r0 + half * 8;
        #pragma unroll
        for (int nt = 0; nt < 4; nt++) {
            int col = nb0 + nt * 8 + cb;
            *(float2*)&pbase[(size_t)row * 64 + col] =
                make_float2(acc[nt][half * 2], acc[nt][half * 2 + 1]);
        }
    }
}

// ---------------- combine partials + bias -> split bf16 h ------------------
__global__ void k_combine(const float* __restrict__ bias) {
    int t = blockIdx.x * 256 + threadIdx.x;
    int idx = t * 2;
    int col = idx & 63;
    float2 p0 = *(const float2*)&g_h1p[idx];
    float2 p1 = *(const float2*)&g_h1p[idx + (size_t)ROWS_TOTAL * 64];
    float f0 = p0.x + p1.x + bias[col];
    float f1 = p0.y + p1.y + bias[col + 1];
    uint32_t lo;
    uint32_t hi = split_pack_hi(f0, f1, lo);
    *(uint32_t*)&g_Hhi[idx] = hi;
    *(uint32_t*)&g_Hlo[idx] = lo;
}

// ------ GEMM2 fused: E = exp(H @ embn^T - 8), per-tile row sums ------------
// grid (64 n-tiles of 64, 128 row-tiles of 128). Warp tile 32x32 (8 warps 4x2).
#define G2_SMEM 50176
__global__ void __launch_bounds__(256, 2) k_gemm2_mma() {
    extern __shared__ char smem[];
    uint32_t sb = smem_u32(smem);
    int tid = threadIdx.x, wid = tid >> 5, lane = tid & 31;
    int nbase = blockIdx.x * 64, rowbase = blockIdx.y * 128;
    const uint32_t AHI = 0, ALO = 16384, BHI = 32768, BLO = 40960, RS = 49152;

    #pragma unroll
    for (int u = 0; u < 4; u++) {
        int f = tid + u * 256;                     // 0..1023
        int row = f >> 3, cq = f & 7;
        uint32_t off = SW128((uint32_t)(row * 128 + cq * 16));
        *(uint4*)(smem + AHI + off) = *(const uint4*)&g_Hhi[(size_t)(rowbase + row) * 64 + cq * 8];
        *(uint4*)(smem + ALO + off) = *(const uint4*)&g_Hlo[(size_t)(rowbase + row) * 64 + cq * 8];
    }
    #pragma unroll
    for (int u = 0; u < 2; u++) {
        int f = tid + u * 256;                     // 0..511
        int n = f >> 3, cq = f & 7;
        uint32_t off = SW128((uint32_t)(n * 128 + cq * 16));
        *(uint4*)(smem + BHI + off) = *(const uint4*)&g_Ehi[(size_t)(nbase + n) * 64 + cq * 8];
        *(uint4*)(smem + BLO + off) = *(const uint4*)&g_Elo[(size_t)(nbase + n) * 64 + cq * 8];
    }
    __syncthreads();

    int warp_m = wid & 3, warp_n = wid >> 2;       // 4 x 2
    int mbase = warp_m * 32, nb0 = warp_n * 32;
    float acc[2][4][4] = {};                       // [mt][n8 block][frag]
    int a_row = lane & 15;
    int a_kadd = (lane >> 4) << 3;
    int b_row = ((lane >> 4) << 3) + (lane & 7);
    int b_kadd = lane & 8;

    #pragma unroll
    for (int ks = 0; ks < 4; ks++) {
        int k0 = ks * 16;
        uint32_t ahi[2][4], alo[2][4];
        #pragma unroll
        for (int mt = 0; mt < 2; mt++) {
            uint32_t aoff = SW128((uint32_t)((mbase + mt * 16 + a_row) * 128 + (k0 + a_kadd) * 2));
            ldsm4(sb + AHI + aoff, ahi[mt][0], ahi[mt][1], ahi[mt][2], ahi[mt][3]);
            ldsm4(sb + ALO + aoff, alo[mt][0], alo[mt][1], alo[mt][2], alo[mt][3]);
        }
        uint32_t bh[2][4], bl[2][4];
        #pragma unroll
        for (int np = 0; np < 2; np++) {
            uint32_t boff = SW128((uint32_t)((nb0 + np * 16 + b_row) * 128 + (k0 + b_kadd) * 2));
            ldsm4(sb + BHI + boff, bh[np][0], bh[np][1], bh[np][2], bh[np][3]);
            ldsm4(sb + BLO + boff, bl[np][0], bl[np][1], bl[np][2], bl[np][3]);
        }
        // pass-ordered: same-acc MMAs are 8 apart
        #pragma unroll
        for (int mt = 0; mt < 2; mt++)
            #pragma unroll
            for (int np = 0; np < 2; np++) {
                mma_bf16(acc[mt][np * 2],     ahi[mt], bh[np]);
                mma_bf16(acc[mt][np * 2 + 1], ahi[mt], bh[np] + 2);
            }
        #pragma unroll
        for (int mt = 0; mt < 2; mt++)
            #pragma unroll
            for (int np = 0; np < 2; np++) {
                mma_bf16(acc[mt][np * 2],     ahi[mt], bl[np]);
                mma_bf16(acc[mt][np * 2 + 1], ahi[mt], bl[np] + 2);
            }
        #pragma unroll
        for (int mt = 0; mt < 2; mt++)
            #pragma unroll
            for (int np = 0; np < 2; np++) {
                mma_bf16(acc[mt][np * 2],     alo[mt], bh[np]);
                mma_bf16(acc[mt][np * 2 + 1], alo[mt], bh[np] + 2);
            }
    }

    // fused epilogue: E = exp(logit - 8) (fp16, MUFU), per-tile fp32 row sums
    float* rs = (float*)(smem + RS);               // [128][2]
    int cb = (lane & 3) * 2;
    #pragma unroll
    for (int mt = 0; mt < 2; mt++) {
        #pragma unroll
        for (int half = 0; half < 2; half++) {
            int rloc = mbase + mt * 16 + half * 8 + (lane >> 2);
            __half* erow = g_E + (size_t)(rowbase + rloc) * NTOT + nbase + nb0;
            float rsum = 0.0f;
            #pragma unroll
            for (int j = 0; j < 4; j++) {
                float e0 = __expf(acc[mt][j][half * 2]     - 8.0f);
                float e1 = __expf(acc[mt][j][half * 2 + 1] - 8.0f);
                rsum += e0 + e1;
                *(__half2*)(erow + j * 8 + cb) = __floats2half2_rn(e0, e1);
            }
            rsum += __shfl_xor_sync(0xffffffffu, rsum, 1);
            rsum += __shfl_xor_sync(0xffffffffu, rsum, 2);
            if ((lane & 3) == 0) rs[rloc * 2 + warp_n] = rsum;
        }
    }
    __syncthreads();
    if (tid < 128)
        g_rsum[(size_t)(rowbase + tid) * 64 + blockIdx.x] = rs[tid * 2] + rs[tid * 2 + 1];
}

// ---------------- group scales: imp / sum(exp) ------------------------------
__global__ void k_rsum_scale(const float* __restrict__ imp) {
    int r = blockIdx.x * 256 + threadIdx.x;        // 0..16383
    const float4* p = (const float4*)(g_rsum + (size_t)r * 64);
    float sC = 0, sQ = 0, sV = 0;
    #pragma unroll
    for (int i = 0; i < 8; i++)  { float4 v = p[i];  sC += (v.x + v.y) + (v.z + v.w); }
    #pragma unroll
    for (int i = 8; i < 12; i++) { float4 v = p[i];  sQ += (v.x + v.y) + (v.z + v.w); }
    #pragma unroll
    for (int i = 12; i < 16; i++){ float4 v = p[i];  sV += (v.x + v.y) + (v.z + v.w); }
    float im = imp[r];
    g_scale[r]                  = im / sC;
    g_scale[ROWS_TOTAL + r]     = im / sQ;
    g_scale[2 * ROWS_TOTAL + r] = im / sV;
}

// ---------------- accumulate d partials (pure streaming) --------------------
__global__ void k_accum() {
    int tid = threadIdx.x;
    int rb = blockIdx.x * 32;
    int grp = (tid < 128) ? 0 : (tid < 192 ? 1 : 2);
    float acc[16] = {};
    for (int ri = 0; ri < 32; ri++) {
        int r = rb + ri;
        float sc = g_scale[grp * ROWS_TOTAL + r];
        const uint4* lp = (const uint4*)(g_E + (size_t)r * NTOT + tid * 16);
        uint4 v0 = lp[0];
        uint4 v1 = lp[1];
        const uint32_t w[8] = {v0.x, v0.y, v0.z, v0.w, v1.x, v1.y, v1.z, v1.w};
        #pragma unroll
        for (int q = 0; q < 8; q++) {
            float2 f = __half22float2(*reinterpret_cast<const __half2*>(&w[q]));
            acc[q * 2]     = fmaf(f.x, sc, acc[q * 2]);
            acc[q * 2 + 1] = fmaf(f.y, sc, acc[q * 2 + 1]);
        }
    }
    float* pp = g_part + (size_t)blockIdx.x * NTOT + tid * 16;
    #pragma unroll
    for (int q = 0; q < 4; q++)
        *(float4*)&pp[q * 4] = make_float4(acc[q * 4], acc[q * 4 + 1],
                                           acc[q * 4 + 2], acc[q * 4 + 3]);
}

__global__ void k_reduce_part() {
    int t = blockIdx.x * 256 + threadIdx.x;
    int b = t >> 12; int n = t & 4095;
    float s = 0.0f;
    #pragma unroll 8
    for (int p = 0; p < 128; p++) s += g_part[(size_t)(b * 128 + p) * NTOT + n];
    g_d[t] = s;
}

// ---------------- top-k sparsify + output ----------------------------------
__global__ void k_topk(float* __restrict__ out) {
    int b = blockIdx.x / 3, g = blockIdx.x % 3;
    int gsize = (g == 0) ? 2048 : 1024;
    int doff = (g == 0) ? 0 : (g == 1 ? 2048 : 3072);
    int K = (g == 0) ? 8 : (g == 1 ? 4 : 6);
    __shared__ float vals[2048];
    __shared__ float rv[256];
    __shared__ int ri[256];
    __shared__ float selv[8];
    __shared__ int seli[8];
    __shared__ float ssum;
    int tid = threadIdx.x;
    for (int i = tid; i < gsize; i += 256) vals[i] = g_d[b * 4096 + doff + i];
    float* ob = out + b * 5120;
    if (g == 0)      { for (int i = tid; i < 2048; i += 256) ob[i] = 0.0f; }
    else if (g == 1) { for (int i = tid; i < 2048; i += 256) ob[2048 + i] = 0.0f; }
    else             { for (int i = tid; i < 1024; i += 256) ob[4096 + i] = 0.0f; }
    __syncthreads();

    for (int kk = 0; kk < K; kk++) {
        float bv = -1e30f; int bi = 0x7fffffff;
        for (int i = tid; i < gsize; i += 256) {
            float v = vals[i];
            if (v > bv || (v == bv && i < bi)) { bv = v; bi = i; }
        }
        rv[tid] = bv; ri[tid] = bi;
        __syncthreads();
        for (int s = 128; s; s >>= 1) {
            if (tid < s) {
                float v2 = rv[tid + s]; int i2 = ri[tid + s];
                if (v2 > rv[tid] || (v2 == rv[tid] && i2 < ri[tid])) { rv[tid] = v2; ri[tid] = i2; }
            }
            __syncthreads();
        }
        if (tid == 0) { selv[kk] = rv[0]; seli[kk] = ri[0]; vals[ri[0]] = -1e30f; }
        __syncthreads();
    }
    if (tid == 0) {
        float s = 0.0f;
        for (int kk = 0; kk < K; kk++) s += selv[kk];
        ssum = 1.0f / (s + 1e-8f);
    }
    __syncthreads();
    if (tid < K) {
        float wv = selv[tid] * ssum;
        int idx = seli[tid];
        if (g == 0) ob[idx] = wv;
        else if (g == 1) { ob[2048 + idx] = wv; ob[3072 + idx] = wv; }
        else ob[4096 + idx] = wv;
    }
}

// ---------------------------------------------------------------------------
extern "C" void kernel_launch(void* const* d_in, const int* in_sizes, int n_in,
                              void* d_out, int out_size) {
    const float *x = nullptr, *imp = nullptr, *W = nullptr, *bias = nullptr, *emb = nullptr;
    for (int i = 0; i < n_in; i++) {
        switch (in_sizes[i]) {
            case 33554432: x    = (const float*)d_in[i]; break;  // 4*4096*2048
            case 16384:    imp  = (const float*)d_in[i]; break;  // 4*4096
            case 131072:   W    = (const float*)d_in[i]; break;  // 2048*64
            case 64:       bias = (const float*)d_in[i]; break;  // 64
            case 262144:   emb  = (const float*)d_in[i]; break;  // 4096*64
            default: break;
        }
    }
    cudaFuncSetAttribute(k_gemm1_mma, cudaFuncAttributeMaxDynamicSharedMemorySize, G1_SMEM);
    cudaFuncSetAttribute(k_gemm2_mma, cudaFuncAttributeMaxDynamicSharedMemorySize, G2_SMEM);

    k_norm_emb<<<512, 256>>>(emb);                 // 0
    k_prep_w<<<512, 256>>>(W);                     // 1
    k_zero<<<64, 256>>>();                         // 2
    k_gemm1_mma<<<dim3(256, 2), 256, G1_SMEM>>>(x);// 3  <- profiled
    k_combine<<<2048, 256>>>(bias);                // 4
    k_gemm2_mma<<<dim3(64, 128), 256, G2_SMEM>>>();// 5
    k_rsum_scale<<<64, 256>>>(imp);                // 6
    k_accum<<<512, 256>>>();                       // 7
    k_reduce_part<<<64, 256>>>();                  // 8
    k_topk<<<12, 256>>>((float*)d_out);            // 9
}

// round 9
// speedup vs baseline: 2.1755x; 1.0370x over previous
#include <cuda_runtime.h>
#include <cuda_fp16.h>
#include <cuda_bf16.h>
#include <cstdint>

#define ROWS_TOTAL 16384
#define DIM 2048
#define NTOT 4096

// ---------------- device scratch (static; no runtime alloc) ----------------
__device__ __align__(16) __nv_bfloat16 g_Ehi[NTOT * 64];
__device__ __align__(16) __nv_bfloat16 g_Elo[NTOT * 64];
__device__ __align__(16) __nv_bfloat16 g_Whi[64 * DIM];
__device__ __align__(16) __nv_bfloat16 g_Wlo[64 * DIM];
__device__ __align__(16) __nv_bfloat16 g_Hhi[(size_t)ROWS_TOTAL * 64];
__device__ __align__(16) __nv_bfloat16 g_Hlo[(size_t)ROWS_TOTAL * 64];
__device__ __align__(16) __half g_E[(size_t)ROWS_TOTAL * NTOT];      // exp(logit-8), 134MB
__device__ __align__(16) float g_rsum[(size_t)ROWS_TOTAL * 64];      // per-tile row sums
__device__ __align__(16) float g_scale[3 * ROWS_TOTAL];              // imp/groupsum
__device__ __align__(16) float g_part[512 * NTOT];
__device__ float g_d[4 * NTOT];

// ---------------- helpers ----------------
__device__ __forceinline__ uint32_t smem_u32(const void* p) {
    uint32_t a;
    asm("{ .reg .u64 t; cvta.to.shared.u64 t, %1; cvt.u32.u64 %0, t; }" : "=r"(a) : "l"(p));
    return a;
}
#define SW128(o) ((o) ^ (((o) >> 3) & 0x70))
#define CP_ASYNC16(dst, src) \
    asm volatile("cp.async.cg.shared.global [%0], [%1], 16;" :: "r"(dst), "l"(src))
#define CP_COMMIT() asm volatile("cp.async.commit_group;" ::: "memory")
#define CP_WAIT0()  asm volatile("cp.async.wait_group 0;" ::: "memory")

__device__ __forceinline__ void ldsm4(uint32_t addr, uint32_t& r0, uint32_t& r1,
                                      uint32_t& r2, uint32_t& r3) {
    asm volatile("ldmatrix.sync.aligned.m8n8.x4.shared.b16 {%0,%1,%2,%3}, [%4];"
                 : "=r"(r0), "=r"(r1), "=r"(r2), "=r"(r3) : "r"(addr));
}
__device__ __forceinline__ void mma_bf16(float* c, const uint32_t* a, const uint32_t* b) {
    asm volatile(
        "mma.sync.aligned.m16n8k16.row.col.f32.bf16.bf16.f32 "
        "{%0,%1,%2,%3}, {%4,%5,%6,%7}, {%8,%9}, {%0,%1,%2,%3};"
        : "+f"(c[0]), "+f"(c[1]), "+f"(c[2]), "+f"(c[3])
        : "r"(a[0]), "r"(a[1]), "r"(a[2]), "r"(a[3]), "r"(b[0]), "r"(b[1]));
}

__device__ __forceinline__ uint32_t split_pack_hi(float a, float b, uint32_t& lo) {
    __nv_bfloat162 h = __floats2bfloat162_rn(a, b);
    float ra = a - __bfloat162float(h.x);
    float rb = b - __bfloat162float(h.y);
    __nv_bfloat162 l = __floats2bfloat162_rn(ra, rb);
    lo = *reinterpret_cast<uint32_t*>(&l);
    return *reinterpret_cast<uint32_t*>(&h);
}

// ---------------- prep kernels ----------------
__global__ void k_norm_emb(const float* __restrict__ emb) {
    int n = blockIdx.x * 8 + (threadIdx.x >> 5);
    int lane = threadIdx.x & 31;
    float v0 = emb[n * 64 + lane];
    float v1 = emb[n * 64 + lane + 32];
    float ss = v0 * v0 + v1 * v1;
    #pragma unroll
    for (int o = 16; o; o >>= 1) ss += __shfl_xor_sync(0xffffffffu, ss, o);
    float inv = rsqrtf(ss);
    float e0 = v0 * inv, e1 = v1 * inv;
    __nv_bfloat16 h0 = __float2bfloat16_rn(e0);
    __nv_bfloat16 h1 = __float2bfloat16_rn(e1);
    g_Ehi[n * 64 + lane] = h0;
    g_Ehi[n * 64 + lane + 32] = h1;
    g_Elo[n * 64 + lane] = __float2bfloat16_rn(e0 - __bfloat162float(h0));
    g_Elo[n * 64 + lane + 32] = __float2bfloat16_rn(e1 - __bfloat162float(h1));
}

__global__ void k_prep_w(const float* __restrict__ W) {
    int t = blockIdx.x * 256 + threadIdx.x;   // t = k*64 + n
    if (t >= DIM * 64) return;
    int k = t >> 6, n = t & 63;
    float v = W[t];
    __nv_bfloat16 h = __float2bfloat16_rn(v);
    g_Whi[n * DIM + k] = h;
    g_Wlo[n * DIM + k] = __float2bfloat16_rn(v - __bfloat162float(h));
}

// ---------------- GEMM1: h = x @ W + b (mma.sync, split bf16, full K) ------
// grid 256 row-tiles of 64. K=2048 in 32 chunks, double-buffered.
// W tiles via cp.async; X via LDG->convert->STS. Epilogue writes split bf16 h.
#define G1_SMEM 65536
__global__ void __launch_bounds__(256, 2) k_gemm1_mma(const float* __restrict__ X,
                                                      const float* __restrict__ bias) {
    extern __shared__ char smem[];
    uint32_t sb = smem_u32(smem);
    int tid = threadIdx.x, wid = tid >> 5, lane = tid & 31;
    int rowbase = blockIdx.x * 64;
    const uint32_t XHI = 0, XLO = 8192, WHI = 16384, WLO = 24576, BUF = 32768;

    float acc[4][4] = {};
    float4 xv[4];

    int warp_m = wid & 3, warp_n = wid >> 2;
    int mbase = warp_m * 16, nb0 = warp_n * 32;
    int a_row = lane & 15;
    int a_kadd = (lane >> 4) << 3;
    int b_row = ((lane >> 4) << 3) + (lane & 7);
    int b_kadd = lane & 8;

    // W tile cp.async: 2 x 16B per array per thread
    auto cpa_w = [&](int c) {
        int kb = c * 64; int b = c & 1;
        #pragma unroll
        for (int u = 0; u < 2; u++) {
            int f = tid + u * 256;             // 0..511
            int n = f >> 3, cq = f & 7;
            uint32_t off = SW128((uint32_t)(n * 128 + cq * 16));
            CP_ASYNC16(sb + WHI + b * BUF + off, &g_Whi[n * DIM + kb + cq * 8]);
            CP_ASYNC16(sb + WLO + b * BUF + off, &g_Wlo[n * DIM + kb + cq * 8]);
        }
        CP_COMMIT();
    };
    auto ldg_x = [&](int c) {
        int kb = c * 64;
        #pragma unroll
        for (int u = 0; u < 4; u++) {
            int f = tid + u * 256;
            int row = f >> 4, kq = f & 15;
            xv[u] = *(const float4*)&X[(size_t)(rowbase + row) * DIM + kb + kq * 4];
        }
    };
    auto sts_x = [&](int c) {
        int b = c & 1;
        #pragma unroll
        for (int u = 0; u < 4; u++) {
            int f = tid + u * 256;
            int row = f >> 4, kq = f & 15;
            uint32_t l0, l1;
            uint32_t h0 = split_pack_hi(xv[u].x, xv[u].y, l0);
            uint32_t h1 = split_pack_hi(xv[u].z, xv[u].w, l1);
            uint32_t off = SW128((uint32_t)(row * 128 + kq * 8));
            *(uint2*)(smem + XHI + b * BUF + off) = make_uint2(h0, h1);
            *(uint2*)(smem + XLO + b * BUF + off) = make_uint2(l0, l1);
        }
    };

    cpa_w(0);
    ldg_x(0);
    sts_x(0);
    CP_WAIT0();
    __syncthreads();
    for (int c = 0; c < 32; c++) {
        if (c + 1 < 32) { cpa_w(c + 1); ldg_x(c + 1); }
        int b = c & 1;
        uint32_t xh = sb + XHI + b * BUF, xl = sb + XLO + b * BUF;
        uint32_t wh = sb + WHI + b * BUF, wl = sb + WLO + b * BUF;
        #pragma unroll
        for (int ks = 0; ks < 4; ks++) {
            int k0 = ks * 16;
            uint32_t ahi[4], alo[4];
            uint32_t aoff = SW128((uint32_t)((mbase + a_row) * 128 + (k0 + a_kadd) * 2));
            ldsm4(xh + aoff, ahi[0], ahi[1], ahi[2], ahi[3]);
            ldsm4(xl + aoff, alo[0], alo[1], alo[2], alo[3]);
            uint32_t bh[2][4], bl[2][4];
            #pragma unroll
            for (int nh = 0; nh < 2; nh++) {
                uint32_t boff = SW128((uint32_t)((nb0 + nh * 16 + b_row) * 128 + (k0 + b_kadd) * 2));
                ldsm4(wh + boff, bh[nh][0], bh[nh][1], bh[nh][2], bh[nh][3]);
                ldsm4(wl + boff, bl[nh][0], bl[nh][1], bl[nh][2], bl[nh][3]);
            }
            #pragma unroll
            for (int nh = 0; nh < 2; nh++) {
                mma_bf16(acc[nh * 2],     ahi, bh[nh]);
                mma_bf16(acc[nh * 2 + 1], ahi, bh[nh] + 2);
            }
            #pragma unroll
            for (int nh = 0; nh < 2; nh++) {
                mma_bf16(acc[nh * 2],     ahi, bl[nh]);
                mma_bf16(acc[nh * 2 + 1], ahi, bl[nh] + 2);
            }
            #pragma unroll
            for (int nh = 0; nh < 2; nh++) {
                mma_bf16(acc[nh * 2],     alo, bh[nh]);
                mma_bf16(acc[nh * 2 + 1], alo, bh[nh] + 2);
            }
        }
        if (c + 1 < 32) sts_x(c + 1);
        CP_WAIT0();
        __syncthreads();
    }

    // epilogue: add bias, split to bf16 hi/lo, store h
    int r0 = rowbase + mbase + (lane >> 2);
    int cb = (lane & 3) * 2;
    #pragma unroll
    for (int half = 0; half < 2; half++) {
        int row = r0 + half * 8;
        size_t ro = (size_t)row * 64;
        #pragma unroll
        for (int nt = 0; nt < 4; nt++) {
            int col = nb0 + nt * 8 + cb;
            float f0 = acc[nt][half * 2]     + bias[col];
            float f1 = acc[nt][half * 2 + 1] + bias[col + 1];
            uint32_t lo;
            uint32_t hi = split_pack_hi(f0, f1, lo);
            *(uint32_t*)&g_Hhi[ro + col] = hi;
            *(uint32_t*)&g_Hlo[ro + col] = lo;
        }
    }
}

// ------ GEMM2 fused: E = exp(H @ embn^T - 8), per-tile row sums ------------
// grid (64 n-tiles of 64, 128 row-tiles of 128). Warp tile 32x32 (8 warps 4x2).
#define G2_SMEM 50176
__global__ void __launch_bounds__(256, 2) k_gemm2_mma() {
    extern __shared__ char smem[];
    uint32_t sb = smem_u32(smem);
    int tid = threadIdx.x, wid = tid >> 5, lane = tid & 31;
    int nbase = blockIdx.x * 64, rowbase = blockIdx.y * 128;
    const uint32_t AHI = 0, ALO = 16384, BHI = 32768, BLO = 40960, RS = 49152;

    #pragma unroll
    for (int u = 0; u < 4; u++) {
        int f = tid + u * 256;                     // 0..1023
        int row = f >> 3, cq = f & 7;
        uint32_t off = SW128((uint32_t)(row * 128 + cq * 16));
        *(uint4*)(smem + AHI + off) = *(const uint4*)&g_Hhi[(size_t)(rowbase + row) * 64 + cq * 8];
        *(uint4*)(smem + ALO + off) = *(const uint4*)&g_Hlo[(size_t)(rowbase + row) * 64 + cq * 8];
    }
    #pragma unroll
    for (int u = 0; u < 2; u++) {
        int f = tid + u * 256;                     // 0..511
        int n = f >> 3, cq = f & 7;
        uint32_t off = SW128((uint32_t)(n * 128 + cq * 16));
        *(uint4*)(smem + BHI + off) = *(const uint4*)&g_Ehi[(size_t)(nbase + n) * 64 + cq * 8];
        *(uint4*)(smem + BLO + off) = *(const uint4*)&g_Elo[(size_t)(nbase + n) * 64 + cq * 8];
    }
    __syncthreads();

    int warp_m = wid & 3, warp_n = wid >> 2;       // 4 x 2
    int mbase = warp_m * 32, nb0 = warp_n * 32;
    float acc[2][4][4] = {};
    int a_row = lane & 15;
    int a_kadd = (lane >> 4) << 3;
    int b_row = ((lane >> 4) << 3) + (lane & 7);
    int b_kadd = lane & 8;

    #pragma unroll
    for (int ks = 0; ks < 4; ks++) {
        int k0 = ks * 16;
        uint32_t ahi[2][4], alo[2][4];
        #pragma unroll
        for (int mt = 0; mt < 2; mt++) {
            uint32_t aoff = SW128((uint32_t)((mbase + mt * 16 + a_row) * 128 + (k0 + a_kadd) * 2));
            ldsm4(sb + AHI + aoff, ahi[mt][0], ahi[mt][1], ahi[mt][2], ahi[mt][3]);
            ldsm4(sb + ALO + aoff, alo[mt][0], alo[mt][1], alo[mt][2], alo[mt][3]);
        }
        uint32_t bh[2][4], bl[2][4];
        #pragma unroll
        for (int np = 0; np < 2; np++) {
            uint32_t boff = SW128((uint32_t)((nb0 + np * 16 + b_row) * 128 + (k0 + b_kadd) * 2));
            ldsm4(sb + BHI + boff, bh[np][0], bh[np][1], bh[np][2], bh[np][3]);
            ldsm4(sb + BLO + boff, bl[np][0], bl[np][1], bl[np][2], bl[np][3]);
        }
        #pragma unroll
        for (int mt = 0; mt < 2; mt++)
            #pragma unroll
            for (int np = 0; np < 2; np++) {
                mma_bf16(acc[mt][np * 2],     ahi[mt], bh[np]);
                mma_bf16(acc[mt][np * 2 + 1], ahi[mt], bh[np] + 2);
            }
        #pragma unroll
        for (int mt = 0; mt < 2; mt++)
            #pragma unroll
            for (int np = 0; np < 2; np++) {
                mma_bf16(acc[mt][np * 2],     ahi[mt], bl[np]);
                mma_bf16(acc[mt][np * 2 + 1], ahi[mt], bl[np] + 2);
            }
        #pragma unroll
        for (int mt = 0; mt < 2; mt++)
            #pragma unroll
            for (int np = 0; np < 2; np++) {
                mma_bf16(acc[mt][np * 2],     alo[mt], bh[np]);
                mma_bf16(acc[mt][np * 2 + 1], alo[mt], bh[np] + 2);
            }
    }

    // fused epilogue: E = exp(logit - 8) (fp16, MUFU), per-tile fp32 row sums
    float* rs = (float*)(smem + RS);               // [128][2]
    int cb = (lane & 3) * 2;
    #pragma unroll
    for (int mt = 0; mt < 2; mt++) {
        #pragma unroll
        for (int half = 0; half < 2; half++) {
            int rloc = mbase + mt * 16 + half * 8 + (lane >> 2);
            __half* erow = g_E + (size_t)(rowbase + rloc) * NTOT + nbase + nb0;
            float rsum = 0.0f;
            #pragma unroll
            for (int j = 0; j < 4; j++) {
                float e0 = __expf(acc[mt][j][half * 2]     - 8.0f);
                float e1 = __expf(acc[mt][j][half * 2 + 1] - 8.0f);
                rsum += e0 + e1;
                *(__half2*)(erow + j * 8 + cb) = __floats2half2_rn(e0, e1);
            }
            rsum += __shfl_xor_sync(0xffffffffu, rsum, 1);
            rsum += __shfl_xor_sync(0xffffffffu, rsum, 2);
            if ((lane & 3) == 0) rs[rloc * 2 + warp_n] = rsum;
        }
    }
    __syncthreads();
    if (tid < 128)
        g_rsum[(size_t)(rowbase + tid) * 64 + blockIdx.x] = rs[tid * 2] + rs[tid * 2 + 1];
}

// ---------------- group scales: imp / sum(exp) ------------------------------
__global__ void k_rsum_scale(const float* __restrict__ imp) {
    int r = blockIdx.x * 256 + threadIdx.x;        // 0..16383
    const float4* p = (const float4*)(g_rsum + (size_t)r * 64);
    float sC = 0, sQ = 0, sV = 0;
    #pragma unroll
    for (int i = 0; i < 8; i++)  { float4 v = p[i];  sC += (v.x + v.y) + (v.z + v.w); }
    #pragma unroll
    for (int i = 8; i < 12; i++) { float4 v = p[i];  sQ += (v.x + v.y) + (v.z + v.w); }
    #pragma unroll
    for (int i = 12; i < 16; i++){ float4 v = p[i];  sV += (v.x + v.y) + (v.z + v.w); }
    float im = imp[r];
    g_scale[r]                  = im / sC;
    g_scale[ROWS_TOTAL + r]     = im / sQ;
    g_scale[2 * ROWS_TOTAL + r] = im / sV;
}

// ---------------- accumulate d partials (pure streaming) --------------------
__global__ void k_accum() {
    int tid = threadIdx.x;
    int rb = blockIdx.x * 32;
    int grp = (tid < 128) ? 0 : (tid < 192 ? 1 : 2);
    float acc[16] = {};
    for (int ri = 0; ri < 32; ri++) {
        int r = rb + ri;
        float sc = g_scale[grp * ROWS_TOTAL + r];
        const uint4* lp = (const uint4*)(g_E + (size_t)r * NTOT + tid * 16);
        uint4 v0 = lp[0];
        uint4 v1 = lp[1];
        const uint32_t w[8] = {v0.x, v0.y, v0.z, v0.w, v1.x, v1.y, v1.z, v1.w};
        #pragma unroll
        for (int q = 0; q < 8; q++) {
            float2 f = __half22float2(*reinterpret_cast<const __half2*>(&w[q]));
            acc[q * 2]     = fmaf(f.x, sc, acc[q * 2]);
            acc[q * 2 + 1] = fmaf(f.y, sc, acc[q * 2 + 1]);
        }
    }
    float* pp = g_part + (size_t)blockIdx.x * NTOT + tid * 16;
    #pragma unroll
    for (int q = 0; q < 4; q++)
        *(float4*)&pp[q * 4] = make_float4(acc[q * 4], acc[q * 4 + 1],
                                           acc[q * 4 + 2], acc[q * 4 + 3]);
}

__global__ void k_reduce_part() {
    int t = blockIdx.x * 256 + threadIdx.x;
    int b = t >> 12; int n = t & 4095;
    float s = 0.0f;
    #pragma unroll 8
    for (int p = 0; p < 128; p++) s += g_part[(size_t)(b * 128 + p) * NTOT + n];
    g_d[t] = s;
}

// ---------------- top-k sparsify + output ----------------------------------
__global__ void k_topk(float* __restrict__ out) {
    int b = blockIdx.x / 3, g = blockIdx.x % 3;
    int gsize = (g == 0) ? 2048 : 1024;
    int doff = (g == 0) ? 0 : (g == 1 ? 2048 : 3072);
    int K = (g == 0) ? 8 : (g == 1 ? 4 : 6);
    __shared__ float vals[2048];
    __shared__ float rv[256];
    __shared__ int ri[256];
    __shared__ float selv[8];
    __shared__ int seli[8];
    __shared__ float ssum;
    int tid = threadIdx.x;
    for (int i = tid; i < gsize; i += 256) vals[i] = g_d[b * 4096 + doff + i];
    float* ob = out + b * 5120;
    if (g == 0)      { for (int i = tid; i < 2048; i += 256) ob[i] = 0.0f; }
    else if (g == 1) { for (int i = tid; i < 2048; i += 256) ob[2048 + i] = 0.0f; }
    else             { for (int i = tid; i < 1024; i += 256) ob[4096 + i] = 0.0f; }
    __syncthreads();

    for (int kk = 0; kk < K; kk++) {
        float bv = -1e30f; int bi = 0x7fffffff;
        for (int i = tid; i < gsize; i += 256) {
            float v = vals[i];
            if (v > bv || (v == bv && i < bi)) { bv = v; bi = i; }
        }
        rv[tid] = bv; ri[tid] = bi;
        __syncthreads();
        for (int s = 128; s; s >>= 1) {
            if (tid < s) {
                float v2 = rv[tid + s]; int i2 = ri[tid + s];
                if (v2 > rv[tid] || (v2 == rv[tid] && i2 < ri[tid])) { rv[tid] = v2; ri[tid] = i2; }
            }
            __syncthreads();
        }
        if (tid == 0) { selv[kk] = rv[0]; seli[kk] = ri[0]; vals[ri[0]] = -1e30f; }
        __syncthreads();
    }
    if (tid == 0) {
        float s = 0.0f;
        for (int kk = 0; kk < K; kk++) s += selv[kk];
        ssum = 1.0f / (s + 1e-8f);
    }
    __syncthreads();
    if (tid < K) {
        float wv = selv[tid] * ssum;
        int idx = seli[tid];
        if (g == 0) ob[idx] = wv;
        else if (g == 1) { ob[2048 + idx] = wv; ob[3072 + idx] = wv; }
        else ob[4096 + idx] = wv;
    }
}

// ---------------------------------------------------------------------------
extern "C" void kernel_launch(void* const* d_in, const int* in_sizes, int n_in,
                              void* d_out, int out_size) {
    const float *x = nullptr, *imp = nullptr, *W = nullptr, *bias = nullptr, *emb = nullptr;
    for (int i = 0; i < n_in; i++) {
        switch (in_sizes[i]) {
            case 33554432: x    = (const float*)d_in[i]; break;  // 4*4096*2048
            case 16384:    imp  = (const float*)d_in[i]; break;  // 4*4096
            case 131072:   W    = (const float*)d_in[i]; break;  // 2048*64
            case 64:       bias = (const float*)d_in[i]; break;  // 64
            case 262144:   emb  = (const float*)d_in[i]; break;  // 4096*64
            default: break;
        }
    }
    cudaFuncSetAttribute(k_gemm1_mma, cudaFuncAttributeMaxDynamicSharedMemorySize, G1_SMEM);
    cudaFuncSetAttribute(k_gemm2_mma, cudaFuncAttributeMaxDynamicSharedMemorySize, G2_SMEM);

    k_norm_emb<<<512, 256>>>(emb);                   // 0
    k_prep_w<<<512, 256>>>(W);                       // 1
    k_gemm1_mma<<<256, 256, G1_SMEM>>>(x, bias);     // 2
    k_gemm2_mma<<<dim3(64, 128), 256, G2_SMEM>>>();  // 3  <- profiled
    k_rsum_scale<<<64, 256>>>(imp);                  // 4
    k_accum<<<512, 256>>>();                         // 5
    k_reduce_part<<<64, 256>>>();                    // 6
    k_topk<<<12, 256>>>((float*)d_out);              // 7
}

// round 10
// speedup vs baseline: 2.3118x; 1.0626x over previous
#include <cuda_runtime.h>
#include <cuda_fp16.h>
#include <cuda_bf16.h>
#include <cstdint>

#define ROWS_TOTAL 16384
#define DIM 2048
#define NTOT 4096

// ---------------- device scratch (static; no runtime alloc) ----------------
__device__ __align__(16) __nv_bfloat16 g_Ehi[NTOT * 64];
__device__ __align__(16) __nv_bfloat16 g_Elo[NTOT * 64];
__device__ __align__(16) __nv_bfloat16 g_Whi[64 * DIM];
__device__ __align__(16) __nv_bfloat16 g_Wlo[64 * DIM];
__device__ __align__(16) __nv_bfloat16 g_Hhi[(size_t)ROWS_TOTAL * 64];
__device__ __align__(16) __nv_bfloat16 g_Hlo[(size_t)ROWS_TOTAL * 64];
__device__ __align__(16) __half g_E[(size_t)ROWS_TOTAL * NTOT];      // exp(logit-8), 134MB
__device__ __align__(16) float g_rsum[(size_t)ROWS_TOTAL * 64];      // per-tile row sums
__device__ __align__(16) float g_scale[3 * ROWS_TOTAL];              // imp/groupsum
__device__ __align__(16) float g_part[512 * NTOT];
__device__ float g_d[4 * NTOT];

// ---------------- helpers ----------------
__device__ __forceinline__ uint32_t smem_u32(const void* p) {
    uint32_t a;
    asm("{ .reg .u64 t; cvta.to.shared.u64 t, %1; cvt.u32.u64 %0, t; }" : "=r"(a) : "l"(p));
    return a;
}
#define SW128(o) ((o) ^ (((o) >> 3) & 0x70))
#define CP_ASYNC16(dst, src) \
    asm volatile("cp.async.cg.shared.global [%0], [%1], 16;" :: "r"(dst), "l"(src))
#define CP_COMMIT() asm volatile("cp.async.commit_group;" ::: "memory")
#define CP_WAIT0()  asm volatile("cp.async.wait_group 0;" ::: "memory")

__device__ __forceinline__ void ldsm4(uint32_t addr, uint32_t& r0, uint32_t& r1,
                                      uint32_t& r2, uint32_t& r3) {
    asm volatile("ldmatrix.sync.aligned.m8n8.x4.shared.b16 {%0,%1,%2,%3}, [%4];"
                 : "=r"(r0), "=r"(r1), "=r"(r2), "=r"(r3) : "r"(addr));
}
__device__ __forceinline__ void mma_bf16(float* c, const uint32_t* a, const uint32_t* b) {
    asm volatile(
        "mma.sync.aligned.m16n8k16.row.col.f32.bf16.bf16.f32 "
        "{%0,%1,%2,%3}, {%4,%5,%6,%7}, {%8,%9}, {%0,%1,%2,%3};"
        : "+f"(c[0]), "+f"(c[1]), "+f"(c[2]), "+f"(c[3])
        : "r"(a[0]), "r"(a[1]), "r"(a[2]), "r"(a[3]), "r"(b[0]), "r"(b[1]));
}

__device__ __forceinline__ uint32_t split_pack_hi(float a, float b, uint32_t& lo) {
    __nv_bfloat162 h = __floats2bfloat162_rn(a, b);
    float ra = a - __bfloat162float(h.x);
    float rb = b - __bfloat162float(h.y);
    __nv_bfloat162 l = __floats2bfloat162_rn(ra, rb);
    lo = *reinterpret_cast<uint32_t*>(&l);
    return *reinterpret_cast<uint32_t*>(&h);
}

// ---------------- prep kernels ----------------
__global__ void k_norm_emb(const float* __restrict__ emb) {
    int n = blockIdx.x * 8 + (threadIdx.x >> 5);
    int lane = threadIdx.x & 31;
    float v0 = emb[n * 64 + lane];
    float v1 = emb[n * 64 + lane + 32];
    float ss = v0 * v0 + v1 * v1;
    #pragma unroll
    for (int o = 16; o; o >>= 1) ss += __shfl_xor_sync(0xffffffffu, ss, o);
    float inv = rsqrtf(ss);
    float e0 = v0 * inv, e1 = v1 * inv;
    __nv_bfloat16 h0 = __float2bfloat16_rn(e0);
    __nv_bfloat16 h1 = __float2bfloat16_rn(e1);
    g_Ehi[n * 64 + lane] = h0;
    g_Ehi[n * 64 + lane + 32] = h1;
    g_Elo[n * 64 + lane] = __float2bfloat16_rn(e0 - __bfloat162float(h0));
    g_Elo[n * 64 + lane + 32] = __float2bfloat16_rn(e1 - __bfloat162float(h1));
}

__global__ void k_prep_w(const float* __restrict__ W) {
    int t = blockIdx.x * 256 + threadIdx.x;   // t = k*64 + n
    if (t >= DIM * 64) return;
    int k = t >> 6, n = t & 63;
    float v = W[t];
    __nv_bfloat16 h = __float2bfloat16_rn(v);
    g_Whi[n * DIM + k] = h;
    g_Wlo[n * DIM + k] = __float2bfloat16_rn(v - __bfloat162float(h));
}

// ---------------- GEMM1: h = x @ W + b (mma.sync, split bf16, full K) ------
#define G1_SMEM 65536
__global__ void __launch_bounds__(256, 2) k_gemm1_mma(const float* __restrict__ X,
                                                      const float* __restrict__ bias) {
    extern __shared__ char smem[];
    uint32_t sb = smem_u32(smem);
    int tid = threadIdx.x, wid = tid >> 5, lane = tid & 31;
    int rowbase = blockIdx.x * 64;
    const uint32_t XHI = 0, XLO = 8192, WHI = 16384, WLO = 24576, BUF = 32768;

    float acc[4][4] = {};
    float4 xv[4];

    int warp_m = wid & 3, warp_n = wid >> 2;
    int mbase = warp_m * 16, nb0 = warp_n * 32;
    int a_row = lane & 15;
    int a_kadd = (lane >> 4) << 3;
    int b_row = ((lane >> 4) << 3) + (lane & 7);
    int b_kadd = lane & 8;

    auto cpa_w = [&](int c) {
        int kb = c * 64; int b = c & 1;
        #pragma unroll
        for (int u = 0; u < 2; u++) {
            int f = tid + u * 256;
            int n = f >> 3, cq = f & 7;
            uint32_t off = SW128((uint32_t)(n * 128 + cq * 16));
            CP_ASYNC16(sb + WHI + b * BUF + off, &g_Whi[n * DIM + kb + cq * 8]);
            CP_ASYNC16(sb + WLO + b * BUF + off, &g_Wlo[n * DIM + kb + cq * 8]);
        }
        CP_COMMIT();
    };
    auto ldg_x = [&](int c) {
        int kb = c * 64;
        #pragma unroll
        for (int u = 0; u < 4; u++) {
            int f = tid + u * 256;
            int row = f >> 4, kq = f & 15;
            xv[u] = *(const float4*)&X[(size_t)(rowbase + row) * DIM + kb + kq * 4];
        }
    };
    auto sts_x = [&](int c) {
        int b = c & 1;
        #pragma unroll
        for (int u = 0; u < 4; u++) {
            int f = tid + u * 256;
            int row = f >> 4, kq = f & 15;
            uint32_t l0, l1;
            uint32_t h0 = split_pack_hi(xv[u].x, xv[u].y, l0);
            uint32_t h1 = split_pack_hi(xv[u].z, xv[u].w, l1);
            uint32_t off = SW128((uint32_t)(row * 128 + kq * 8));
            *(uint2*)(smem + XHI + b * BUF + off) = make_uint2(h0, h1);
            *(uint2*)(smem + XLO + b * BUF + off) = make_uint2(l0, l1);
        }
    };

    cpa_w(0);
    ldg_x(0);
    sts_x(0);
    CP_WAIT0();
    __syncthreads();
    for (int c = 0; c < 32; c++) {
        if (c + 1 < 32) { cpa_w(c + 1); ldg_x(c + 1); }
        int b = c & 1;
        uint32_t xh = sb + XHI + b * BUF, xl = sb + XLO + b * BUF;
        uint32_t wh = sb + WHI + b * BUF, wl = sb + WLO + b * BUF;
        #pragma unroll
        for (int ks = 0; ks < 4; ks++) {
            int k0 = ks * 16;
            uint32_t ahi[4], alo[4];
            uint32_t aoff = SW128((uint32_t)((mbase + a_row) * 128 + (k0 + a_kadd) * 2));
            ldsm4(xh + aoff, ahi[0], ahi[1], ahi[2], ahi[3]);
            ldsm4(xl + aoff, alo[0], alo[1], alo[2], alo[3]);
            uint32_t bh[2][4], bl[2][4];
            #pragma unroll
            for (int nh = 0; nh < 2; nh++) {
                uint32_t boff = SW128((uint32_t)((nb0 + nh * 16 + b_row) * 128 + (k0 + b_kadd) * 2));
                ldsm4(wh + boff, bh[nh][0], bh[nh][1], bh[nh][2], bh[nh][3]);
                ldsm4(wl + boff, bl[nh][0], bl[nh][1], bl[nh][2], bl[nh][3]);
            }
            #pragma unroll
            for (int nh = 0; nh < 2; nh++) {
                mma_bf16(acc[nh * 2],     ahi, bh[nh]);
                mma_bf16(acc[nh * 2 + 1], ahi, bh[nh] + 2);
            }
            #pragma unroll
            for (int nh = 0; nh < 2; nh++) {
                mma_bf16(acc[nh * 2],     ahi, bl[nh]);
                mma_bf16(acc[nh * 2 + 1], ahi, bl[nh] + 2);
            }
            #pragma unroll
            for (int nh = 0; nh < 2; nh++) {
                mma_bf16(acc[nh * 2],     alo, bh[nh]);
                mma_bf16(acc[nh * 2 + 1], alo, bh[nh] + 2);
            }
        }
        if (c + 1 < 32) sts_x(c + 1);
        CP_WAIT0();
        __syncthreads();
    }

    int r0 = rowbase + mbase + (lane >> 2);
    int cb = (lane & 3) * 2;
    #pragma unroll
    for (int half = 0; half < 2; half++) {
        int row = r0 + half * 8;
        size_t ro = (size_t)row * 64;
        #pragma unroll
        for (int nt = 0; nt < 4; nt++) {
            int col = nb0 + nt * 8 + cb;
            float f0 = acc[nt][half * 2]     + bias[col];
            float f1 = acc[nt][half * 2 + 1] + bias[col + 1];
            uint32_t lo;
            uint32_t hi = split_pack_hi(f0, f1, lo);
            *(uint32_t*)&g_Hhi[ro + col] = hi;
            *(uint32_t*)&g_Hlo[ro + col] = lo;
        }
    }
}

// ------ GEMM2 fused: E = exp(H @ embn^T - 8), per-tile row sums ------------
// grid (64 n-tiles of 64, 128 row-tiles of 128). 128 threads (4 warps, 2m x 2n),
// warp tile 64x32 -> MMA:ldsm4 ratio 4:1 (was 1.5:1).
#define G2_SMEM 50176
__global__ void __launch_bounds__(128) k_gemm2_mma() {
    extern __shared__ char smem[];
    uint32_t sb = smem_u32(smem);
    int tid = threadIdx.x, wid = tid >> 5, lane = tid & 31;
    int nbase = blockIdx.x * 64, rowbase = blockIdx.y * 128;
    const uint32_t AHI = 0, ALO = 16384, BHI = 32768, BLO = 40960, RS = 49152;

    #pragma unroll
    for (int u = 0; u < 8; u++) {
        int f = tid + u * 128;                     // 0..1023
        int row = f >> 3, cq = f & 7;
        uint32_t off = SW128((uint32_t)(row * 128 + cq * 16));
        *(uint4*)(smem + AHI + off) = *(const uint4*)&g_Hhi[(size_t)(rowbase + row) * 64 + cq * 8];
        *(uint4*)(smem + ALO + off) = *(const uint4*)&g_Hlo[(size_t)(rowbase + row) * 64 + cq * 8];
    }
    #pragma unroll
    for (int u = 0; u < 4; u++) {
        int f = tid + u * 128;                     // 0..511
        int n = f >> 3, cq = f & 7;
        uint32_t off = SW128((uint32_t)(n * 128 + cq * 16));
        *(uint4*)(smem + BHI + off) = *(const uint4*)&g_Ehi[(size_t)(nbase + n) * 64 + cq * 8];
        *(uint4*)(smem + BLO + off) = *(const uint4*)&g_Elo[(size_t)(nbase + n) * 64 + cq * 8];
    }
    __syncthreads();

    int warp_m = wid & 1, warp_n = wid >> 1;       // 2 x 2
    int mbase = warp_m * 64, nb0 = warp_n * 32;
    float acc[4][4][4] = {};                       // [mt][np*2+nh][frag]
    int a_row = lane & 15;
    int a_kadd = (lane >> 4) << 3;
    int b_row = ((lane >> 4) << 3) + (lane & 7);
    int b_kadd = lane & 8;

    #pragma unroll
    for (int ks = 0; ks < 4; ks++) {
        int k0 = ks * 16;
        uint32_t ahi[4][4], alo[4][4];
        #pragma unroll
        for (int mt = 0; mt < 4; mt++) {
            uint32_t aoff = SW128((uint32_t)((mbase + mt * 16 + a_row) * 128 + (k0 + a_kadd) * 2));
            ldsm4(sb + AHI + aoff, ahi[mt][0], ahi[mt][1], ahi[mt][2], ahi[mt][3]);
            ldsm4(sb + ALO + aoff, alo[mt][0], alo[mt][1], alo[mt][2], alo[mt][3]);
        }
        uint32_t bh[2][4], bl[2][4];
        #pragma unroll
        for (int np = 0; np < 2; np++) {
            uint32_t boff = SW128((uint32_t)((nb0 + np * 16 + b_row) * 128 + (k0 + b_kadd) * 2));
            ldsm4(sb + BHI + boff, bh[np][0], bh[np][1], bh[np][2], bh[np][3]);
            ldsm4(sb + BLO + boff, bl[np][0], bl[np][1], bl[np][2], bl[np][3]);
        }
        // 3 passes, same-acc MMAs 16 apart
        #pragma unroll
        for (int mt = 0; mt < 4; mt++)
            #pragma unroll
            for (int np = 0; np < 2; np++) {
                mma_bf16(acc[mt][np * 2],     ahi[mt], bh[np]);
                mma_bf16(acc[mt][np * 2 + 1], ahi[mt], bh[np] + 2);
            }
        #pragma unroll
        for (int mt = 0; mt < 4; mt++)
            #pragma unroll
            for (int np = 0; np < 2; np++) {
                mma_bf16(acc[mt][np * 2],     ahi[mt], bl[np]);
                mma_bf16(acc[mt][np * 2 + 1], ahi[mt], bl[np] + 2);
            }
        #pragma unroll
        for (int mt = 0; mt < 4; mt++)
            #pragma unroll
            for (int np = 0; np < 2; np++) {
                mma_bf16(acc[mt][np * 2],     alo[mt], bh[np]);
                mma_bf16(acc[mt][np * 2 + 1], alo[mt], bh[np] + 2);
            }
    }

    // fused epilogue: E = exp(logit - 8) (fp16, MUFU), per-tile fp32 row sums
    float* rs = (float*)(smem + RS);               // [128][2]
    int cb = (lane & 3) * 2;
    #pragma unroll
    for (int mt = 0; mt < 4; mt++) {
        #pragma unroll
        for (int half = 0; half < 2; half++) {
            int rloc = mbase + mt * 16 + half * 8 + (lane >> 2);
            __half* erow = g_E + (size_t)(rowbase + rloc) * NTOT + nbase + nb0;
            float rsum = 0.0f;
            #pragma unroll
            for (int j = 0; j < 4; j++) {
                float e0 = __expf(acc[mt][j][half * 2]     - 8.0f);
                float e1 = __expf(acc[mt][j][half * 2 + 1] - 8.0f);
                rsum += e0 + e1;
                *(__half2*)(erow + j * 8 + cb) = __floats2half2_rn(e0, e1);
            }
            rsum += __shfl_xor_sync(0xffffffffu, rsum, 1);
            rsum += __shfl_xor_sync(0xffffffffu, rsum, 2);
            if ((lane & 3) == 0) rs[rloc * 2 + warp_n] = rsum;
        }
    }
    __syncthreads();
    g_rsum[(size_t)(rowbase + tid) * 64 + blockIdx.x] = rs[tid * 2] + rs[tid * 2 + 1];
}

// ---------------- group scales: imp / sum(exp) ------------------------------
__global__ void k_rsum_scale(const float* __restrict__ imp) {
    int r = blockIdx.x * 256 + threadIdx.x;        // 0..16383
    const float4* p = (const float4*)(g_rsum + (size_t)r * 64);
    float sC = 0, sQ = 0, sV = 0;
    #pragma unroll
    for (int i = 0; i < 8; i++)  { float4 v = p[i];  sC += (v.x + v.y) + (v.z + v.w); }
    #pragma unroll
    for (int i = 8; i < 12; i++) { float4 v = p[i];  sQ += (v.x + v.y) + (v.z + v.w); }
    #pragma unroll
    for (int i = 12; i < 16; i++){ float4 v = p[i];  sV += (v.x + v.y) + (v.z + v.w); }
    float im = imp[r];
    g_scale[r]                  = im / sC;
    g_scale[ROWS_TOTAL + r]     = im / sQ;
    g_scale[2 * ROWS_TOTAL + r] = im / sV;
}

// ---------------- accumulate d partials (pure streaming) --------------------
__global__ void k_accum() {
    int tid = threadIdx.x;
    int rb = blockIdx.x * 32;
    int grp = (tid < 128) ? 0 : (tid < 192 ? 1 : 2);
    float acc[16] = {};
    for (int ri = 0; ri < 32; ri++) {
        int r = rb + ri;
        float sc = g_scale[grp * ROWS_TOTAL + r];
        const uint4* lp = (const uint4*)(g_E + (size_t)r * NTOT + tid * 16);
        uint4 v0 = lp[0];
        uint4 v1 = lp[1];
        const uint32_t w[8] = {v0.x, v0.y, v0.z, v0.w, v1.x, v1.y, v1.z, v1.w};
        #pragma unroll
        for (int q = 0; q < 8; q++) {
            float2 f = __half22float2(*reinterpret_cast<const __half2*>(&w[q]));
            acc[q * 2]     = fmaf(f.x, sc, acc[q * 2]);
            acc[q * 2 + 1] = fmaf(f.y, sc, acc[q * 2 + 1]);
        }
    }
    float* pp = g_part + (size_t)blockIdx.x * NTOT + tid * 16;
    #pragma unroll
    for (int q = 0; q < 4; q++)
        *(float4*)&pp[q * 4] = make_float4(acc[q * 4], acc[q * 4 + 1],
                                           acc[q * 4 + 2], acc[q * 4 + 3]);
}

__global__ void k_reduce_part() {
    int t = blockIdx.x * 256 + threadIdx.x;
    int b = t >> 12; int n = t & 4095;
    float s = 0.0f;
    #pragma unroll 8
    for (int p = 0; p < 128; p++) s += g_part[(size_t)(b * 128 + p) * NTOT + n];
    g_d[t] = s;
}

// ---------------- top-k sparsify + output ----------------------------------
__global__ void k_topk(float* __restrict__ out) {
    int b = blockIdx.x / 3, g = blockIdx.x % 3;
    int gsize = (g == 0) ? 2048 : 1024;
    int doff = (g == 0) ? 0 : (g == 1 ? 2048 : 3072);
    int K = (g == 0) ? 8 : (g == 1 ? 4 : 6);
    __shared__ float vals[2048];
    __shared__ float rv[256];
    __shared__ int ri[256];
    __shared__ float selv[8];
    __shared__ int seli[8];
    __shared__ float ssum;
    int tid = threadIdx.x;
    for (int i = tid; i < gsize; i += 256) vals[i] = g_d[b * 4096 + doff + i];
    float* ob = out + b * 5120;
    if (g == 0)      { for (int i = tid; i < 2048; i += 256) ob[i] = 0.0f; }
    else if (g == 1) { for (int i = tid; i < 2048; i += 256) ob[2048 + i] = 0.0f; }
    else             { for (int i = tid; i < 1024; i += 256) ob[4096 + i] = 0.0f; }
    __syncthreads();

    for (int kk = 0; kk < K; kk++) {
        float bv = -1e30f; int bi = 0x7fffffff;
        for (int i = tid; i < gsize; i += 256) {
            float v = vals[i];
            if (v > bv || (v == bv && i < bi)) { bv = v; bi = i; }
        }
        rv[tid] = bv; ri[tid] = bi;
        __syncthreads();
        for (int s = 128; s; s >>= 1) {
            if (tid < s) {
                float v2 = rv[tid + s]; int i2 = ri[tid + s];
                if (v2 > rv[tid] || (v2 == rv[tid] && i2 < ri[tid])) { rv[tid] = v2; ri[tid] = i2; }
            }
            __syncthreads();
        }
        if (tid == 0) { selv[kk] = rv[0]; seli[kk] = ri[0]; vals[ri[0]] = -1e30f; }
        __syncthreads();
    }
    if (tid == 0) {
        float s = 0.0f;
        for (int kk = 0; kk < K; kk++) s += selv[kk];
        ssum = 1.0f / (s + 1e-8f);
    }
    __syncthreads();
    if (tid < K) {
        float wv = selv[tid] * ssum;
        int idx = seli[tid];
        if (g == 0) ob[idx] = wv;
        else if (g == 1) { ob[2048 + idx] = wv; ob[3072 + idx] = wv; }
        else ob[4096 + idx] = wv;
    }
}

// ---------------------------------------------------------------------------
extern "C" void kernel_launch(void* const* d_in, const int* in_sizes, int n_in,
                              void* d_out, int out_size) {
    const float *x = nullptr, *imp = nullptr, *W = nullptr, *bias = nullptr, *emb = nullptr;
    for (int i = 0; i < n_in; i++) {
        switch (in_sizes[i]) {
            case 33554432: x    = (const float*)d_in[i]; break;  // 4*4096*2048
            case 16384:    imp  = (const float*)d_in[i]; break;  // 4*4096
            case 131072:   W    = (const float*)d_in[i]; break;  // 2048*64
            case 64:       bias = (const float*)d_in[i]; break;  // 64
            case 262144:   emb  = (const float*)d_in[i]; break;  // 4096*64
            default: break;
        }
    }
    cudaFuncSetAttribute(k_gemm1_mma, cudaFuncAttributeMaxDynamicSharedMemorySize, G1_SMEM);
    cudaFuncSetAttribute(k_gemm2_mma, cudaFuncAttributeMaxDynamicSharedMemorySize, G2_SMEM);

    k_norm_emb<<<512, 256>>>(emb);                   // 0
    k_prep_w<<<512, 256>>>(W);                       // 1
    k_gemm1_mma<<<256, 256, G1_SMEM>>>(x, bias);     // 2
    k_gemm2_mma<<<dim3(64, 128), 128, G2_SMEM>>>();  // 3  <- profiled
    k_rsum_scale<<<64, 256>>>(imp);                  // 4
    k_accum<<<512, 256>>>();                         // 5
    k_reduce_part<<<64, 256>>>();                    // 6
    k_topk<<<12, 256>>>((float*)d_out);              // 7
}